// round 8
// baseline (speedup 1.0000x reference)
#include <cuda_runtime.h>
#include <stdint.h>

#define B_    512
#define T_    76
#define HIST  10
#define H_    256
#define NSTEP 64
#define MLPH  15000
#define K1    130
#define NCH2  469
#define CHF   (NCH2 * 2048)

__device__ __align__(16) float g_mlpf[8][CHF];
__device__ __align__(16) float g_W2f[(size_t)64 * CHF];
__device__ __align__(16) float g_h[2][8][8][16384];
__device__ __align__(16) float g_h7row[8][64][256];
__device__ __align__(16) float g_c[8][B_][H_];
__device__ __align__(16) float g_Wp[4194304];   // [l][bh16][s2][kc8][2048]
__device__ __align__(16) float g_Wih0p[16][1024];
__device__ unsigned g_prog[128];

__device__ __forceinline__ float tf32f(float x) {
    uint32_t r; asm("cvt.rna.tf32.f32 %0, %1;" : "=r"(r) : "f"(x));
    return __uint_as_float(r);
}
#define U(x) __float_as_uint(x)
__device__ __forceinline__ void mma8(float c[4], uint32_t a0, uint32_t a1, uint32_t a2, uint32_t a3,
                                     uint32_t b0, uint32_t b1) {
    asm volatile("mma.sync.aligned.m16n8k8.row.col.f32.tf32.tf32.f32 "
                 "{%0,%1,%2,%3},{%4,%5,%6,%7},{%8,%9},{%0,%1,%2,%3};\n"
                 : "+f"(c[0]), "+f"(c[1]), "+f"(c[2]), "+f"(c[3])
                 : "r"(a0), "r"(a1), "r"(a2), "r"(a3), "r"(b0), "r"(b1));
}
__device__ __forceinline__ float sigf(float x) { return __fdividef(1.f, 1.f + __expf(-x)); }
__device__ __forceinline__ float tanhf_(float x) { return 2.f * sigf(2.f * x) - 1.f; }
__device__ __forceinline__ void cpa16(void* s, const void* g) {
    uint32_t sa = (uint32_t)__cvta_generic_to_shared(s);
    asm volatile("cp.async.cg.shared.global [%0], [%1], 16;" :: "r"(sa), "l"(g));
}
#define CP_COMMIT() asm volatile("cp.async.commit_group;\n")
#define CP_WAIT(n)  asm volatile("cp.async.wait_group %0;\n" :: "n"(n))

__device__ __forceinline__ int hfrag(int r, int k) {
    return ((((k >> 3) * 4 + (r >> 4)) * 32 + (r & 7) * 4 + (k & 3)) << 2)
           + ((r >> 3) & 1) + (((k >> 2) & 1) << 1);
}

__device__ __forceinline__ void mma_frag(const float4* Ac, const float4* Bc,
                                         float (&acc)[4][4], int wm, int wn, int lane) {
#pragma unroll
    for (int k8 = 0; k8 < 4; k8++) {
        float4 a  = Ac[(k8 * 4 + wm) * 32 + lane];
        float4 b0 = Bc[((k8 * 2 + wn) * 2 + 0) * 32 + lane];
        float4 b1 = Bc[((k8 * 2 + wn) * 2 + 1) * 32 + lane];
        mma8(acc[0], U(a.x), U(a.y), U(a.z), U(a.w), U(b0.x), U(b0.y));
        mma8(acc[1], U(a.x), U(a.y), U(a.z), U(a.w), U(b0.z), U(b0.w));
        mma8(acc[2], U(a.x), U(a.y), U(a.z), U(a.w), U(b1.x), U(b1.y));
        mma8(acc[3], U(a.x), U(a.y), U(a.z), U(a.w), U(b1.z), U(b1.w));
    }
}

// ---- prep: rollout weights, gate-interleaved fragments ----
__global__ void __launch_bounds__(256) k_prep_w(const float* __restrict__ Whh0,
                                                const float* __restrict__ Wih,
                                                const float* __restrict__ Whh) {
    const int idx = blockIdx.x * 256 + threadIdx.x;
    const int comp = idx & 3, c4 = (idx >> 2) & 511;
    const int lane = c4 & 31, half = (c4 >> 5) & 1, wn = (c4 >> 6) & 1, k8 = (c4 >> 7) & 3;
    const int kc = (idx >> 11) & 7, s = (idx >> 14) & 1, bh = (idx >> 15) & 15, l = (idx >> 19) & 7;
    const int gc = (wn * 4 + half * 2 + (comp >> 1)) * 8 + (lane >> 2);
    const int n = ((gc >> 3) & 3) * 256 + bh * 16 + (gc >> 5) * 8 + (gc & 7);
    const int k = kc * 32 + k8 * 8 + (comp & 1) * 4 + (lane & 3);
    float v = 0.f;
    if (l == 0) { if (s == 0) v = Whh0[n * 256 + k]; }
    else v = (s == 0) ? Whh[(size_t)(l - 1) * 262144 + n * 256 + k]
                      : Wih[(size_t)(l - 1) * 262144 + n * 256 + k];
    g_Wp[idx] = tf32f(v);
}

// ---- prep: W2 -> fragments via coalesced smem transpose ----
__global__ void __launch_bounds__(256) k_prep_w2t(const float* __restrict__ W2) {
    const int bn = blockIdx.x / NCH2, kc = blockIdx.x - bn * NCH2;
    const int tid = threadIdx.x;
    __shared__ float s[64][33];
#pragma unroll
    for (int q = 0; q < 2; q++) {
        const int f = tid + q * 256;
        const int n = f >> 3, kq = (f & 7) << 2;
        const int gk = kc * 32 + kq;
        float4 v;
        const float* p = W2 + (size_t)(bn * 64 + n) * MLPH;
        if (gk + 3 < MLPH) v = *(const float4*)(p + gk);
        else {
            v.x = (gk + 0 < MLPH) ? p[gk + 0] : 0.f;
            v.y = (gk + 1 < MLPH) ? p[gk + 1] : 0.f;
            v.z = (gk + 2 < MLPH) ? p[gk + 2] : 0.f;
            v.w = (gk + 3 < MLPH) ? p[gk + 3] : 0.f;
        }
        s[n][kq] = v.x; s[n][kq + 1] = v.y; s[n][kq + 2] = v.z; s[n][kq + 3] = v.w;
    }
    __syncthreads();
    float4* dst = ((float4*)g_W2f) + (size_t)(bn * NCH2 + kc) * 512;
#pragma unroll
    for (int q = 0; q < 2; q++) {
        const int j = tid + q * 256;
        const int lane = j & 31, half = (j >> 5) & 1, wn = (j >> 6) & 1, k8 = (j >> 7) & 3;
        float4 v; float* pv = (float*)&v;
#pragma unroll
        for (int c = 0; c < 4; c++) {
            const int gc = (wn * 4 + half * 2 + (c >> 1)) * 8 + (lane >> 2);
            const int k = k8 * 8 + (c & 1) * 4 + (lane & 3);
            pv[c] = tf32f(s[gc][k]);
        }
        dst[j] = v;
    }
}

__global__ void __launch_bounds__(256) k_prep_small(const float* __restrict__ Wih0) {
    const int i = blockIdx.x * 256 + threadIdx.x;
    if (i < 16384) {
        const int bh = i >> 10, pos = i & 1023;
        const int comp = pos & 3, c4 = pos >> 2;
        const int lane = c4 & 31, half = (c4 >> 5) & 1, wn = (c4 >> 6) & 1, k8 = (c4 >> 7) & 1;
        const int gc = (wn * 4 + half * 2 + (comp >> 1)) * 8 + (lane >> 2);
        const int n = ((gc >> 3) & 3) * 256 + bh * 16 + (gc >> 5) * 8 + (gc & 7);
        const int k = k8 * 8 + (comp & 1) * 4 + (lane & 3);
        g_Wih0p[bh][pos] = (k < 14) ? tf32f(Wih0[n * 14 + k]) : 0.f;
    } else if (i < 16384 + 4096) {
        const int j = i - 16384;
        const int rg = j >> 9, rem = j & 511;
        g_mlpf[rg][468 * 2048 + hfrag(rem >> 3, 24 + (rem & 7))] = 0.f;
    } else if (i < 16384 + 4096 + 128) {
        g_prog[i - 16384 - 4096] = 0u;
    }
}

// ---- GEMM1 ----
__global__ void __launch_bounds__(256) k_gemm1(const float* __restrict__ states,
                                               const float* __restrict__ acts,
                                               const float* __restrict__ W1,
                                               const float* __restrict__ b1) {
    const int bm = blockIdx.x & 15, bn = blockIdx.x >> 4, n0 = bn * 128;
    const int tid = threadIdx.x;
    __shared__ float enc_s[32][132];
    __shared__ float w_s[128][33];
    for (int i = tid; i < 32 * K1; i += 256) {
        const int r = i / K1, k = i % K1, b = bm * 32 + r;
        const int tt = k / 13, j = k % 13;
        enc_s[r][k] = (j < 9) ? states[(b * T_ + tt) * 12 + 3 + j]
                              : acts[(b * T_ + tt) * 4 + (j - 9)];
    }
    float acc[4][4];
#pragma unroll
    for (int a = 0; a < 4; a++)
#pragma unroll
        for (int b = 0; b < 4; b++) acc[a][b] = 0.f;
    const int tr = tid >> 5, tc = tid & 31;
    for (int k0 = 0; k0 < K1; k0 += 32) {
        const int kn = min(32, K1 - k0);
        __syncthreads();
        for (int i = tid; i < 4096; i += 256) {
            const int c = i >> 5, kk = i & 31, n = n0 + c;
            w_s[c][kk] = (kk < kn && n < MLPH) ? W1[n * K1 + k0 + kk] : 0.f;
        }
        __syncthreads();
        for (int kk = 0; kk < kn; kk++) {
            float a[4], w[4];
#pragma unroll
            for (int x = 0; x < 4; x++) a[x] = enc_s[tr + 8 * x][k0 + kk];
#pragma unroll
            for (int y = 0; y < 4; y++) w[y] = w_s[tc + 32 * y][kk];
#pragma unroll
            for (int x = 0; x < 4; x++)
#pragma unroll
                for (int y = 0; y < 4; y++) acc[x][y] += a[x] * w[y];
        }
    }
#pragma unroll
    for (int x = 0; x < 4; x++)
#pragma unroll
        for (int y = 0; y < 4; y++) {
            const int b = bm * 32 + tr + 8 * x, n = n0 + tc + 32 * y;
            if (n < MLPH)
                g_mlpf[b >> 6][(n >> 5) * 2048 + hfrag(b & 63, n & 31)] =
                    tf32f(fmaxf(acc[x][y] + b1[n], 0.f));
        }
}

// ---- GEMM2: fragment pipeline ----
__global__ void __launch_bounds__(256, 2) k_gemm2(const float* __restrict__ b2) {
    const int bm = blockIdx.x & 7, bn = blockIdx.x >> 3;
    const int tid = threadIdx.x;
    const int warp = tid >> 5, lane = tid & 31;
    const int wm = warp >> 1, wn = warp & 1;
    const int g = lane >> 2, tq = lane & 3;
    extern __shared__ __align__(16) float4 s4[];
    float4* A4 = s4; float4* B4 = s4 + 3 * 512;
    const float4* Asrc = (const float4*)g_mlpf[bm];
    const float4* Bsrc = ((const float4*)g_W2f) + (size_t)bn * (NCH2 * 512);

    float acc[4][4];
#pragma unroll
    for (int j = 0; j < 4; j++)
#pragma unroll
        for (int d = 0; d < 4; d++) acc[j][d] = 0.f;

    auto stage = [&](int s, int c) {
        cpa16(&A4[s * 512 + tid], Asrc + (size_t)c * 512 + tid);
        cpa16(&A4[s * 512 + tid + 256], Asrc + (size_t)c * 512 + tid + 256);
        cpa16(&B4[s * 512 + tid], Bsrc + (size_t)c * 512 + tid);
        cpa16(&B4[s * 512 + tid + 256], Bsrc + (size_t)c * 512 + tid + 256);
        CP_COMMIT();
    };
    stage(0, 0); stage(1, 1);
    for (int c = 0; c < NCH2; c++) {
        if (c < NCH2 - 1) CP_WAIT(1); else CP_WAIT(0);
        __syncthreads();
        if (c + 2 < NCH2) stage((c + 2) % 3, c + 2);
        mma_frag(A4 + (c % 3) * 512, B4 + (c % 3) * 512, acc, wm, wn, lane);
    }
#pragma unroll
    for (int j = 0; j < 4; j++)
#pragma unroll
        for (int d = 0; d < 4; d++) {
            const int r = wm * 16 + g + ((d & 2) ? 8 : 0);
            const int p = (wn * 4 + j) * 8 + tq * 2 + (d & 1);
            const int n = bn * 64 + p;
            const float v = acc[j][d] + b2[n];
            const int l = n >> 9, rem = n & 511;
            if (rem < H_) g_h[1][l][bm][hfrag(r, rem)] = tf32f(v);
            else          g_c[l][bm * 64 + r][rem - H_] = v;
        }
}

// ---- rollout: fused 8-chunk layer pipeline, spin at layer head ----
__global__ void __launch_bounds__(256) k_rollout(
    const float* __restrict__ states, const float* __restrict__ acts,
    const float* __restrict__ dts,
    const float* __restrict__ bih0, const float* __restrict__ bhh0,
    const float* __restrict__ bih, const float* __restrict__ bhh,
    const float* __restrict__ Wfc, const float* __restrict__ bfc,
    float* __restrict__ out)
{
    const int rg = blockIdx.x >> 4, bh = blockIdx.x & 15;
    const int tid = threadIdx.x;
    const int warp = tid >> 5, lane = tid & 31;
    const int wm = warp >> 1, wn = warp & 1;
    const int g = lane >> 2, tq = lane & 3;
    const int row0 = rg * 64, hc0 = bh * 16;

    extern __shared__ __align__(16) float sm[];
    float4* A4 = (float4*)sm;                    // 3*1024 f4
    float4* B4 = (float4*)(sm + 12288);          // 3*1024 f4
    float4* AX = (float4*)(sm + 24576);          // 256 f4
    float4* BX = (float4*)(sm + 25600);          // 256 f4
    float (*Gs)[68]   = (float(*)[68])(sm + 26624);
    float (*xs)[16]   = (float(*)[16])(sm + 30976);
    float (*bias)[64] = (float(*)[64])(sm + 32000);

    cpa16(&BX[tid], &((const float4*)g_Wih0p[bh])[tid]);
    CP_COMMIT();

    for (int i = tid; i < 512; i += 256) {
        const int l = i >> 6, gc = i & 63;
        const int n = (gc >> 4) * 256 + hc0 + (gc & 15);
        bias[l][gc] = (l == 0) ? __ldg(&bih0[n]) + __ldg(&bhh0[n])
                               : __ldg(&bih[(l - 1) * 1024 + n]) + __ldg(&bhh[(l - 1) * 1024 + n]);
    }
    float c_reg[8][4];
#pragma unroll
    for (int l = 0; l < 8; l++)
#pragma unroll
        for (int d = 0; d < 4; d++) {
            const int r = wm * 16 + g + ((d & 2) ? 8 : 0);
            const int hc = wn * 8 + tq * 2 + (d & 1);
            c_reg[l][d] = __ldcg(&g_c[l][row0 + r][hc0 + hc]);
        }
    for (int i = tid; i < 576; i += 256) {
        const int r = i / 9, j = i % 9;
        xs[r][1 + j] = states[((row0 + r) * T_ + HIST) * 12 + 3 + j];
    }
    if (tid < 128) xs[tid >> 1][14 + (tid & 1)] = 0.f;
    CP_WAIT(0);
    __syncthreads();

    const float4* Wp4 = (const float4*)g_Wp;
    auto stage64 = [&](int s, const float4* Ag, const float4* Bg) {
#pragma unroll
        for (int q = 0; q < 4; q++) {
            cpa16(&A4[s * 1024 + tid + q * 256], Ag + tid + q * 256);
            cpa16(&B4[s * 1024 + tid + q * 256], Bg + tid + q * 256);
        }
        CP_COMMIT();
    };

    for (int t = 0; t < NSTEP; t++) {
        const int cur = t & 1, old = cur ^ 1;
        if (tid < 64) xs[tid][0] = dts[(row0 + tid) * T_ + HIST + 1 + t];
        { const int r = tid >> 2, j = tid & 3;
          xs[r][10 + j] = acts[((row0 + r) * T_ + HIST + t) * 4 + j]; }
        __syncthreads();

        for (int l = 0; l < 8; l++) {
            float acc[4][4];
#pragma unroll
            for (int j = 0; j < 4; j++)
#pragma unroll
                for (int d = 0; d < 4; d++) acc[j][d] = 0.f;

            const float4* Bb = Wp4 + (size_t)(l * 16 + bh) * 8192;
            const float4* Ah0 = (const float4*)&g_h[old][l][rg][0];     // Whh operand
            const float4* Ah1 = (l > 0) ? (const float4*)&g_h[cur][l - 1][rg][0] : Ah0;
            const int nch = (l == 0) ? 4 : 8;

            // pre-stage dependency-free Whh chunks 0,1; loads fly during spin
            stage64(0, Ah0, Bb);
            stage64(1, Ah0 + 1024, Bb + 1024);

            if (l == 0) {
                {   // x fragments
                    const int k8 = tid >> 7, wmx = (tid >> 5) & 3, ln = tid & 31;
                    const int gg = ln >> 2, tt = ln & 3;
                    float4 v;
                    v.x = tf32f(xs[wmx * 16 + gg][k8 * 8 + tt]);
                    v.y = tf32f(xs[wmx * 16 + gg + 8][k8 * 8 + tt]);
                    v.z = tf32f(xs[wmx * 16 + gg][k8 * 8 + tt + 4]);
                    v.w = tf32f(xs[wmx * 16 + gg + 8][k8 * 8 + tt + 4]);
                    AX[tid] = v;
                }
                __syncthreads();
#pragma unroll
                for (int k8 = 0; k8 < 2; k8++) {
                    float4 a  = AX[(k8 * 4 + wm) * 32 + lane];
                    float4 b0 = BX[((k8 * 2 + wn) * 2 + 0) * 32 + lane];
                    float4 b1 = BX[((k8 * 2 + wn) * 2 + 1) * 32 + lane];
                    mma8(acc[0], U(a.x), U(a.y), U(a.z), U(a.w), U(b0.x), U(b0.y));
                    mma8(acc[1], U(a.x), U(a.y), U(a.z), U(a.w), U(b0.z), U(b0.w));
                    mma8(acc[2], U(a.x), U(a.y), U(a.z), U(a.w), U(b1.x), U(b1.y));
                    mma8(acc[3], U(a.x), U(a.y), U(a.z), U(a.w), U(b1.z), U(b1.w));
                }
            } else {
                // spin for siblings' layer l-1 (usually instant; Whh loads in flight)
                const unsigned tgt = (unsigned)(t * 8 + l);
                if (tid < 16) {
                    while (((volatile unsigned*)g_prog)[rg * 16 + tid] < tgt) __nanosleep(32);
                    __threadfence();
                }
                __syncthreads();
            }

            // fused pipeline: chunks 0..nch-1 (c<4: Whh/h_old, c>=4: Wih/h_cur[l-1])
            for (int c = 0; c < nch; c++) {
                if (c < nch - 1) CP_WAIT(1); else CP_WAIT(0);
                __syncthreads();
                if (c + 2 < nch) {
                    const int c2 = c + 2;
                    const float4* Ag = (c2 < 4) ? Ah0 + c2 * 1024 : Ah1 + (c2 - 4) * 1024;
                    stage64(c2 % 3, Ag, Bb + c2 * 1024);
                }
                mma_frag(A4 + (c % 3) * 1024,       B4 + (c % 3) * 1024,       acc, wm, wn, lane);
                mma_frag(A4 + (c % 3) * 1024 + 512, B4 + (c % 3) * 1024 + 512, acc, wm, wn, lane);
            }

            // register LSTM epilogue
            float* hdst = &g_h[cur][l][rg][0];
#pragma unroll
            for (int d = 0; d < 4; d++) {
                const int r = wm * 16 + g + ((d & 2) ? 8 : 0);
                const int hc = wn * 8 + tq * 2 + (d & 1);
                const float iG = acc[0][d] + bias[l][hc];
                const float fG = acc[1][d] + bias[l][16 + hc];
                const float gG = acc[2][d] + bias[l][32 + hc];
                const float oG = acc[3][d] + bias[l][48 + hc];
                const float cn = sigf(fG) * c_reg[l][d] + sigf(iG) * tanhf_(gG);
                c_reg[l][d] = cn;
                const float hv = tf32f(sigf(oG) * tanhf_(cn));
                hdst[hfrag(r, hc0 + hc)] = hv;
                if (l == 7) g_h7row[rg][r][hc0 + hc] = hv;
            }
            __threadfence();
            __syncthreads();
            if (tid == 0)
                *(volatile unsigned*)&g_prog[rg * 16 + bh] = (unsigned)(t * 8 + l + 1);
        }

        if (tid < 16) {
            const unsigned tgt = (unsigned)(t * 8 + 8);
            while (((volatile unsigned*)g_prog)[rg * 16 + tid] < tgt) __nanosleep(32);
            __threadfence();
        }
        __syncthreads();

        // fc
        const int r1 = tid >> 3, o1 = tid & 7;
        float pa = __ldg(&bfc[o1]), pb = __ldg(&bfc[o1]);
        float pc = (tid < 64) ? __ldg(&bfc[8]) : 0.f;
        for (int qq = 0; qq < 4; qq++) {
            __syncthreads();
#pragma unroll
            for (int q = 0; q < 4; q++) {
                const int i = tid + 256 * q;
                const int r = i >> 4, kq = (i & 15) << 2;
                float4 v = __ldcg((const float4*)&g_h7row[rg][r][qq * 64 + kq]);
                Gs[r][kq] = v.x; Gs[r][kq + 1] = v.y; Gs[r][kq + 2] = v.z; Gs[r][kq + 3] = v.w;
            }
            __syncthreads();
#pragma unroll 4
            for (int k = 0; k < 64; k++) {
                const float w = __ldg(&Wfc[o1 * 256 + qq * 64 + k]);
                pa += Gs[r1][k] * w;
                pb += Gs[r1 + 32][k] * w;
                if (tid < 64) pc += Gs[tid][k] * __ldg(&Wfc[8 * 256 + qq * 64 + k]);
            }
        }
        __syncthreads();
        xs[r1][1 + o1] = pa;
        xs[r1 + 32][1 + o1] = pb;
        if (tid < 64) xs[tid][9] = pc;
        if (bh == 0) {
            out[(size_t)(row0 + r1) * (NSTEP * 9) + t * 9 + o1] = pa;
            out[(size_t)(row0 + r1 + 32) * (NSTEP * 9) + t * 9 + o1] = pb;
            if (tid < 64) out[(size_t)(row0 + tid) * (NSTEP * 9) + t * 9 + 8] = pc;
        }
        __syncthreads();
    }
}

extern "C" void kernel_launch(void* const* d_in, const int* in_sizes, int n_in,
                              void* d_out, int out_size) {
    const float* states = (const float*)d_in[0];
    const float* acts   = (const float*)d_in[1];
    const float* dts    = (const float*)d_in[2];
    const float* W1     = (const float*)d_in[3];
    const float* b1     = (const float*)d_in[4];
    const float* W2     = (const float*)d_in[5];
    const float* b2     = (const float*)d_in[6];
    const float* Wih0   = (const float*)d_in[7];
    const float* Whh0   = (const float*)d_in[8];
    const float* bih0   = (const float*)d_in[9];
    const float* bhh0   = (const float*)d_in[10];
    const float* Wih    = (const float*)d_in[11];
    const float* Whh    = (const float*)d_in[12];
    const float* bih    = (const float*)d_in[13];
    const float* bhh    = (const float*)d_in[14];
    const float* Wfc    = (const float*)d_in[15];
    const float* bfc    = (const float*)d_in[16];
    float* out = (float*)d_out;

    const int sm2 = 6 * 512 * 16;       // 49152
    const int smr = 32512 * 4;          // 130048
    cudaFuncSetAttribute(k_gemm2, cudaFuncAttributeMaxDynamicSharedMemorySize, sm2);
    cudaFuncSetAttribute(k_rollout, cudaFuncAttributeMaxDynamicSharedMemorySize, smr);

    k_prep_w<<<16384, 256>>>(Whh0, Wih, Whh);
    k_prep_w2t<<<64 * NCH2, 256>>>(W2);
    k_prep_small<<<81, 256>>>(Wih0);
    k_gemm1<<<16 * 118, 256>>>(states, acts, W1, b1);
    k_gemm2<<<512, 256, sm2>>>(b2);
    k_rollout<<<128, 256, smr>>>(states, acts, dts, bih0, bhh0,
                                 bih, bhh, Wfc, bfc, out);
}

// round 9
// speedup vs baseline: 1.2541x; 1.2541x over previous
#include <cuda_runtime.h>
#include <stdint.h>

#define B_    512
#define T_    76
#define HIST  10
#define H_    256
#define NSTEP 64
#define MLPH  15000
#define K1    130
#define NCH2  469
#define CHF   (NCH2 * 2048)

__device__ __align__(16) float g_mlpf[8][CHF];
__device__ __align__(16) float g_W2f[(size_t)64 * CHF];
__device__ __align__(16) float g_h[2][8][8][16384];
__device__ __align__(16) float g_h7row[8][64][256];
__device__ __align__(16) float g_c[8][B_][H_];
__device__ __align__(16) float g_Wp[4194304];   // [l][bh16][s2][kc8][2048]
__device__ __align__(16) float g_Wih0p[16][1024];
__device__ unsigned g_prog[128];

__device__ __forceinline__ float tf32f(float x) {
    uint32_t r; asm("cvt.rna.tf32.f32 %0, %1;" : "=r"(r) : "f"(x));
    return __uint_as_float(r);
}
#define U(x) __float_as_uint(x)
__device__ __forceinline__ void mma8(float c[4], uint32_t a0, uint32_t a1, uint32_t a2, uint32_t a3,
                                     uint32_t b0, uint32_t b1) {
    asm volatile("mma.sync.aligned.m16n8k8.row.col.f32.tf32.tf32.f32 "
                 "{%0,%1,%2,%3},{%4,%5,%6,%7},{%8,%9},{%0,%1,%2,%3};\n"
                 : "+f"(c[0]), "+f"(c[1]), "+f"(c[2]), "+f"(c[3])
                 : "r"(a0), "r"(a1), "r"(a2), "r"(a3), "r"(b0), "r"(b1));
}
__device__ __forceinline__ float sigf(float x) { return __fdividef(1.f, 1.f + __expf(-x)); }
__device__ __forceinline__ float tanhf_(float x) { return 2.f * sigf(2.f * x) - 1.f; }
__device__ __forceinline__ void cpa16(void* s, const void* g) {
    uint32_t sa = (uint32_t)__cvta_generic_to_shared(s);
    asm volatile("cp.async.cg.shared.global [%0], [%1], 16;" :: "r"(sa), "l"(g));
}
#define CP_COMMIT() asm volatile("cp.async.commit_group;\n")
#define CP_WAIT(n)  asm volatile("cp.async.wait_group %0;\n" :: "n"(n))

__device__ __forceinline__ int hfrag(int r, int k) {
    return ((((k >> 3) * 4 + (r >> 4)) * 32 + (r & 7) * 4 + (k & 3)) << 2)
           + ((r >> 3) & 1) + (((k >> 2) & 1) << 1);
}

// 4-warp variant: warp tile 32x32, acc[2][4][4]
__device__ __forceinline__ void mma_frag2(const float4* Ac, const float4* Bc,
                                          float (&acc)[2][4][4], int wm, int wn, int lane) {
#pragma unroll
    for (int k8 = 0; k8 < 4; k8++) {
        float4 a0 = Ac[(k8 * 4 + wm * 2 + 0) * 32 + lane];
        float4 a1 = Ac[(k8 * 4 + wm * 2 + 1) * 32 + lane];
        float4 b0 = Bc[((k8 * 2 + wn) * 2 + 0) * 32 + lane];
        float4 b1 = Bc[((k8 * 2 + wn) * 2 + 1) * 32 + lane];
        mma8(acc[0][0], U(a0.x), U(a0.y), U(a0.z), U(a0.w), U(b0.x), U(b0.y));
        mma8(acc[0][1], U(a0.x), U(a0.y), U(a0.z), U(a0.w), U(b0.z), U(b0.w));
        mma8(acc[0][2], U(a0.x), U(a0.y), U(a0.z), U(a0.w), U(b1.x), U(b1.y));
        mma8(acc[0][3], U(a0.x), U(a0.y), U(a0.z), U(a0.w), U(b1.z), U(b1.w));
        mma8(acc[1][0], U(a1.x), U(a1.y), U(a1.z), U(a1.w), U(b0.x), U(b0.y));
        mma8(acc[1][1], U(a1.x), U(a1.y), U(a1.z), U(a1.w), U(b0.z), U(b0.w));
        mma8(acc[1][2], U(a1.x), U(a1.y), U(a1.z), U(a1.w), U(b1.x), U(b1.y));
        mma8(acc[1][3], U(a1.x), U(a1.y), U(a1.z), U(a1.w), U(b1.z), U(b1.w));
    }
}

// 8-warp variant (gemm2)
__device__ __forceinline__ void mma_frag(const float4* Ac, const float4* Bc,
                                         float (&acc)[4][4], int wm, int wn, int lane) {
#pragma unroll
    for (int k8 = 0; k8 < 4; k8++) {
        float4 a  = Ac[(k8 * 4 + wm) * 32 + lane];
        float4 b0 = Bc[((k8 * 2 + wn) * 2 + 0) * 32 + lane];
        float4 b1 = Bc[((k8 * 2 + wn) * 2 + 1) * 32 + lane];
        mma8(acc[0], U(a.x), U(a.y), U(a.z), U(a.w), U(b0.x), U(b0.y));
        mma8(acc[1], U(a.x), U(a.y), U(a.z), U(a.w), U(b0.z), U(b0.w));
        mma8(acc[2], U(a.x), U(a.y), U(a.z), U(a.w), U(b1.x), U(b1.y));
        mma8(acc[3], U(a.x), U(a.y), U(a.z), U(a.w), U(b1.z), U(b1.w));
    }
}

// ---- prep: rollout weights, gate-interleaved fragments ----
__global__ void __launch_bounds__(256) k_prep_w(const float* __restrict__ Whh0,
                                                const float* __restrict__ Wih,
                                                const float* __restrict__ Whh) {
    const int idx = blockIdx.x * 256 + threadIdx.x;
    const int comp = idx & 3, c4 = (idx >> 2) & 511;
    const int lane = c4 & 31, half = (c4 >> 5) & 1, wn = (c4 >> 6) & 1, k8 = (c4 >> 7) & 3;
    const int kc = (idx >> 11) & 7, s = (idx >> 14) & 1, bh = (idx >> 15) & 15, l = (idx >> 19) & 7;
    const int gc = (wn * 4 + half * 2 + (comp >> 1)) * 8 + (lane >> 2);
    const int n = ((gc >> 3) & 3) * 256 + bh * 16 + (gc >> 5) * 8 + (gc & 7);
    const int k = kc * 32 + k8 * 8 + (comp & 1) * 4 + (lane & 3);
    float v = 0.f;
    if (l == 0) { if (s == 0) v = Whh0[n * 256 + k]; }
    else v = (s == 0) ? Whh[(size_t)(l - 1) * 262144 + n * 256 + k]
                      : Wih[(size_t)(l - 1) * 262144 + n * 256 + k];
    g_Wp[idx] = tf32f(v);
}

// ---- prep: W2 -> fragments via coalesced smem transpose ----
__global__ void __launch_bounds__(256) k_prep_w2t(const float* __restrict__ W2) {
    const int bn = blockIdx.x / NCH2, kc = blockIdx.x - bn * NCH2;
    const int tid = threadIdx.x;
    __shared__ float s[64][33];
#pragma unroll
    for (int q = 0; q < 2; q++) {
        const int f = tid + q * 256;
        const int n = f >> 3, kq = (f & 7) << 2;
        const int gk = kc * 32 + kq;
        float4 v;
        const float* p = W2 + (size_t)(bn * 64 + n) * MLPH;
        if (gk + 3 < MLPH) v = *(const float4*)(p + gk);
        else {
            v.x = (gk + 0 < MLPH) ? p[gk + 0] : 0.f;
            v.y = (gk + 1 < MLPH) ? p[gk + 1] : 0.f;
            v.z = (gk + 2 < MLPH) ? p[gk + 2] : 0.f;
            v.w = (gk + 3 < MLPH) ? p[gk + 3] : 0.f;
        }
        s[n][kq] = v.x; s[n][kq + 1] = v.y; s[n][kq + 2] = v.z; s[n][kq + 3] = v.w;
    }
    __syncthreads();
    float4* dst = ((float4*)g_W2f) + (size_t)(bn * NCH2 + kc) * 512;
#pragma unroll
    for (int q = 0; q < 2; q++) {
        const int j = tid + q * 256;
        const int lane = j & 31, half = (j >> 5) & 1, wn = (j >> 6) & 1, k8 = (j >> 7) & 3;
        float4 v; float* pv = (float*)&v;
#pragma unroll
        for (int c = 0; c < 4; c++) {
            const int gc = (wn * 4 + half * 2 + (c >> 1)) * 8 + (lane >> 2);
            const int k = k8 * 8 + (c & 1) * 4 + (lane & 3);
            pv[c] = tf32f(s[gc][k]);
        }
        dst[j] = v;
    }
}

__global__ void __launch_bounds__(256) k_prep_small(const float* __restrict__ Wih0) {
    const int i = blockIdx.x * 256 + threadIdx.x;
    if (i < 16384) {
        const int bh = i >> 10, pos = i & 1023;
        const int comp = pos & 3, c4 = pos >> 2;
        const int lane = c4 & 31, half = (c4 >> 5) & 1, wn = (c4 >> 6) & 1, k8 = (c4 >> 7) & 1;
        const int gc = (wn * 4 + half * 2 + (comp >> 1)) * 8 + (lane >> 2);
        const int n = ((gc >> 3) & 3) * 256 + bh * 16 + (gc >> 5) * 8 + (gc & 7);
        const int k = k8 * 8 + (comp & 1) * 4 + (lane & 3);
        g_Wih0p[bh][pos] = (k < 14) ? tf32f(Wih0[n * 14 + k]) : 0.f;
    } else if (i < 16384 + 4096) {
        const int j = i - 16384;
        const int rg = j >> 9, rem = j & 511;
        g_mlpf[rg][468 * 2048 + hfrag(rem >> 3, 24 + (rem & 7))] = 0.f;
    } else if (i < 16384 + 4096 + 128) {
        g_prog[i - 16384 - 4096] = 0u;
    }
}

// ---- GEMM1 ----
__global__ void __launch_bounds__(256) k_gemm1(const float* __restrict__ states,
                                               const float* __restrict__ acts,
                                               const float* __restrict__ W1,
                                               const float* __restrict__ b1) {
    const int bm = blockIdx.x & 15, bn = blockIdx.x >> 4, n0 = bn * 128;
    const int tid = threadIdx.x;
    __shared__ float enc_s[32][132];
    __shared__ float w_s[128][33];
    for (int i = tid; i < 32 * K1; i += 256) {
        const int r = i / K1, k = i % K1, b = bm * 32 + r;
        const int tt = k / 13, j = k % 13;
        enc_s[r][k] = (j < 9) ? states[(b * T_ + tt) * 12 + 3 + j]
                              : acts[(b * T_ + tt) * 4 + (j - 9)];
    }
    float acc[4][4];
#pragma unroll
    for (int a = 0; a < 4; a++)
#pragma unroll
        for (int b = 0; b < 4; b++) acc[a][b] = 0.f;
    const int tr = tid >> 5, tc = tid & 31;
    for (int k0 = 0; k0 < K1; k0 += 32) {
        const int kn = min(32, K1 - k0);
        __syncthreads();
        for (int i = tid; i < 4096; i += 256) {
            const int c = i >> 5, kk = i & 31, n = n0 + c;
            w_s[c][kk] = (kk < kn && n < MLPH) ? W1[n * K1 + k0 + kk] : 0.f;
        }
        __syncthreads();
        for (int kk = 0; kk < kn; kk++) {
            float a[4], w[4];
#pragma unroll
            for (int x = 0; x < 4; x++) a[x] = enc_s[tr + 8 * x][k0 + kk];
#pragma unroll
            for (int y = 0; y < 4; y++) w[y] = w_s[tc + 32 * y][kk];
#pragma unroll
            for (int x = 0; x < 4; x++)
#pragma unroll
                for (int y = 0; y < 4; y++) acc[x][y] += a[x] * w[y];
        }
    }
#pragma unroll
    for (int x = 0; x < 4; x++)
#pragma unroll
        for (int y = 0; y < 4; y++) {
            const int b = bm * 32 + tr + 8 * x, n = n0 + tc + 32 * y;
            if (n < MLPH)
                g_mlpf[b >> 6][(n >> 5) * 2048 + hfrag(b & 63, n & 31)] =
                    tf32f(fmaxf(acc[x][y] + b1[n], 0.f));
        }
}

// ---- GEMM2 ----
__global__ void __launch_bounds__(256, 2) k_gemm2(const float* __restrict__ b2) {
    const int bm = blockIdx.x & 7, bn = blockIdx.x >> 3;
    const int tid = threadIdx.x;
    const int warp = tid >> 5, lane = tid & 31;
    const int wm = warp >> 1, wn = warp & 1;
    const int g = lane >> 2, tq = lane & 3;
    extern __shared__ __align__(16) float4 s4[];
    float4* A4 = s4; float4* B4 = s4 + 3 * 512;
    const float4* Asrc = (const float4*)g_mlpf[bm];
    const float4* Bsrc = ((const float4*)g_W2f) + (size_t)bn * (NCH2 * 512);

    float acc[4][4];
#pragma unroll
    for (int j = 0; j < 4; j++)
#pragma unroll
        for (int d = 0; d < 4; d++) acc[j][d] = 0.f;

    auto stage = [&](int s, int c) {
        cpa16(&A4[s * 512 + tid], Asrc + (size_t)c * 512 + tid);
        cpa16(&A4[s * 512 + tid + 256], Asrc + (size_t)c * 512 + tid + 256);
        cpa16(&B4[s * 512 + tid], Bsrc + (size_t)c * 512 + tid);
        cpa16(&B4[s * 512 + tid + 256], Bsrc + (size_t)c * 512 + tid + 256);
        CP_COMMIT();
    };
    stage(0, 0); stage(1, 1);
    for (int c = 0; c < NCH2; c++) {
        if (c < NCH2 - 1) CP_WAIT(1); else CP_WAIT(0);
        __syncthreads();
        if (c + 2 < NCH2) stage((c + 2) % 3, c + 2);
        mma_frag(A4 + (c % 3) * 512, B4 + (c % 3) * 512, acc, wm, wn, lane);
    }
#pragma unroll
    for (int j = 0; j < 4; j++)
#pragma unroll
        for (int d = 0; d < 4; d++) {
            const int r = wm * 16 + g + ((d & 2) ? 8 : 0);
            const int p = (wn * 4 + j) * 8 + tq * 2 + (d & 1);
            const int n = bn * 64 + p;
            const float v = acc[j][d] + b2[n];
            const int l = n >> 9, rem = n & 511;
            if (rem < H_) g_h[1][l][bm][hfrag(r, rem)] = tf32f(v);
            else          g_c[l][bm * 64 + r][rem - H_] = v;
        }
}

// ---- rollout: 4 warps (2x2, 32x32 warp tiles), fused pipeline, spin at c==2 ----
__global__ void __launch_bounds__(128) k_rollout(
    const float* __restrict__ states, const float* __restrict__ acts,
    const float* __restrict__ dts,
    const float* __restrict__ bih0, const float* __restrict__ bhh0,
    const float* __restrict__ bih, const float* __restrict__ bhh,
    const float* __restrict__ Wfc, const float* __restrict__ bfc,
    float* __restrict__ out)
{
    const int rg = blockIdx.x >> 4, bh = blockIdx.x & 15;
    const int tid = threadIdx.x;
    const int warp = tid >> 5, lane = tid & 31;
    const int wm = warp >> 1, wn = warp & 1;
    const int g = lane >> 2, tq = lane & 3;
    const int row0 = rg * 64, hc0 = bh * 16;

    extern __shared__ __align__(16) float sm[];
    float4* A4 = (float4*)sm;                    // 3*1024 f4
    float4* B4 = (float4*)(sm + 12288);          // 3*1024 f4
    float4* AX = (float4*)(sm + 24576);          // 256 f4
    float4* BX = (float4*)(sm + 25600);          // 256 f4
    float (*Gs)[68]   = (float(*)[68])(sm + 26624);   // 64x68
    float (*xs)[16]   = (float(*)[16])(sm + 30976);   // 64x16
    float (*bias)[64] = (float(*)[64])(sm + 32000);   // 8x64
    float* Wfcs       = sm + 32512;                    // 9*256

#pragma unroll
    for (int q = 0; q < 2; q++)
        cpa16(&BX[tid + q * 128], &((const float4*)g_Wih0p[bh])[tid + q * 128]);
    CP_COMMIT();

    for (int i = tid; i < 512; i += 128) {
        const int l = i >> 6, gc = i & 63;
        const int n = (gc >> 4) * 256 + hc0 + (gc & 15);
        bias[l][gc] = (l == 0) ? __ldg(&bih0[n]) + __ldg(&bhh0[n])
                               : __ldg(&bih[(l - 1) * 1024 + n]) + __ldg(&bhh[(l - 1) * 1024 + n]);
    }
    for (int i = tid; i < 2304; i += 128) Wfcs[i] = __ldg(&Wfc[i]);

    float c_reg[8][2][4];
#pragma unroll
    for (int l = 0; l < 8; l++)
#pragma unroll
        for (int mi = 0; mi < 2; mi++)
#pragma unroll
            for (int d = 0; d < 4; d++) {
                const int r = wm * 32 + mi * 16 + g + ((d & 2) ? 8 : 0);
                const int hc = wn * 8 + tq * 2 + (d & 1);
                c_reg[l][mi][d] = __ldcg(&g_c[l][row0 + r][hc0 + hc]);
            }
    for (int i = tid; i < 576; i += 128) {
        const int r = i / 9, j = i % 9;
        xs[r][1 + j] = states[((row0 + r) * T_ + HIST) * 12 + 3 + j];
    }
    { xs[tid >> 1][14 + (tid & 1)] = 0.f; }
    CP_WAIT(0);
    __syncthreads();

    const float4* Wp4 = (const float4*)g_Wp;
    auto stage64 = [&](int s, const float4* Ag, const float4* Bg) {
#pragma unroll
        for (int q = 0; q < 8; q++) {
            cpa16(&A4[s * 1024 + tid + q * 128], Ag + tid + q * 128);
            cpa16(&B4[s * 1024 + tid + q * 128], Bg + tid + q * 128);
        }
        CP_COMMIT();
    };

    for (int t = 0; t < NSTEP; t++) {
        const int cur = t & 1, old = cur ^ 1;
        if (tid < 64) xs[tid][0] = dts[(row0 + tid) * T_ + HIST + 1 + t];
#pragma unroll
        for (int q = 0; q < 2; q++) {
            const int i = tid + q * 128;
            xs[i >> 2][10 + (i & 3)] = acts[((row0 + (i >> 2)) * T_ + HIST + t) * 4 + (i & 3)];
        }
        __syncthreads();

        for (int l = 0; l < 8; l++) {
            float acc[2][4][4];
#pragma unroll
            for (int mi = 0; mi < 2; mi++)
#pragma unroll
                for (int j = 0; j < 4; j++)
#pragma unroll
                    for (int d = 0; d < 4; d++) acc[mi][j][d] = 0.f;

            const float4* Bb = Wp4 + (size_t)(l * 16 + bh) * 8192;
            const float4* Ah0 = (const float4*)&g_h[old][l][rg][0];
            const float4* Ah1 = (l > 0) ? (const float4*)&g_h[cur][l - 1][rg][0] : Ah0;
            const int nch = (l == 0) ? 4 : 8;

            stage64(0, Ah0, Bb);
            stage64(1, Ah0 + 1024, Bb + 1024);

            if (l == 0) {   // x-tile
#pragma unroll
                for (int q = 0; q < 2; q++) {
                    const int idx = tid + q * 128;
                    const int k8 = idx >> 7, mt = (idx >> 5) & 3, ln = idx & 31;
                    const int gg = ln >> 2, tt = ln & 3;
                    float4 v;
                    v.x = tf32f(xs[mt * 16 + gg][k8 * 8 + tt]);
                    v.y = tf32f(xs[mt * 16 + gg + 8][k8 * 8 + tt]);
                    v.z = tf32f(xs[mt * 16 + gg][k8 * 8 + tt + 4]);
                    v.w = tf32f(xs[mt * 16 + gg + 8][k8 * 8 + tt + 4]);
                    AX[idx] = v;
                }
                __syncthreads();
#pragma unroll
                for (int k8 = 0; k8 < 2; k8++) {
                    float4 b0 = BX[((k8 * 2 + wn) * 2 + 0) * 32 + lane];
                    float4 b1 = BX[((k8 * 2 + wn) * 2 + 1) * 32 + lane];
#pragma unroll
                    for (int mi = 0; mi < 2; mi++) {
                        float4 a = AX[(k8 * 4 + wm * 2 + mi) * 32 + lane];
                        mma8(acc[mi][0], U(a.x), U(a.y), U(a.z), U(a.w), U(b0.x), U(b0.y));
                        mma8(acc[mi][1], U(a.x), U(a.y), U(a.z), U(a.w), U(b0.z), U(b0.w));
                        mma8(acc[mi][2], U(a.x), U(a.y), U(a.z), U(a.w), U(b1.x), U(b1.y));
                        mma8(acc[mi][3], U(a.x), U(a.y), U(a.z), U(a.w), U(b1.z), U(b1.w));
                    }
                }
            }

            for (int c = 0; c < nch; c++) {
                if (c < nch - 1) CP_WAIT(1); else CP_WAIT(0);
                __syncthreads();
                if (l > 0 && c == 2) {   // dependency needed for staging chunk 4
                    const unsigned tgt = (unsigned)(t * 8 + l);
                    if (tid < 16) {
                        while (((volatile unsigned*)g_prog)[rg * 16 + tid] < tgt) __nanosleep(32);
                        __threadfence();
                    }
                    __syncthreads();
                }
                if (c + 2 < nch) {
                    const int c2 = c + 2;
                    const float4* Ag = (c2 < 4) ? Ah0 + c2 * 1024 : Ah1 + (c2 - 4) * 1024;
                    stage64(c2 % 3, Ag, Bb + c2 * 1024);
                }
                mma_frag2(A4 + (c % 3) * 1024,       B4 + (c % 3) * 1024,       acc, wm, wn, lane);
                mma_frag2(A4 + (c % 3) * 1024 + 512, B4 + (c % 3) * 1024 + 512, acc, wm, wn, lane);
            }

            // register LSTM epilogue
            float* hdst = &g_h[cur][l][rg][0];
#pragma unroll
            for (int mi = 0; mi < 2; mi++)
#pragma unroll
                for (int d = 0; d < 4; d++) {
                    const int r = wm * 32 + mi * 16 + g + ((d & 2) ? 8 : 0);
                    const int hc = wn * 8 + tq * 2 + (d & 1);
                    const float iG = acc[mi][0][d] + bias[l][hc];
                    const float fG = acc[mi][1][d] + bias[l][16 + hc];
                    const float gG = acc[mi][2][d] + bias[l][32 + hc];
                    const float oG = acc[mi][3][d] + bias[l][48 + hc];
                    const float cn = sigf(fG) * c_reg[l][mi][d] + sigf(iG) * tanhf_(gG);
                    c_reg[l][mi][d] = cn;
                    const float hv = tf32f(sigf(oG) * tanhf_(cn));
                    hdst[hfrag(r, hc0 + hc)] = hv;
                    if (l == 7) g_h7row[rg][r][hc0 + hc] = hv;
                }
            __threadfence();
            __syncthreads();
            if (tid == 0)
                *(volatile unsigned*)&g_prog[rg * 16 + bh] = (unsigned)(t * 8 + l + 1);
        }

        if (tid < 16) {
            const unsigned tgt = (unsigned)(t * 8 + 8);
            while (((volatile unsigned*)g_prog)[rg * 16 + tid] < tgt) __nanosleep(32);
            __threadfence();
        }
        __syncthreads();

        // fc: row = tid>>1, out-half = tid&1
        const int r2 = tid >> 1;
        const int oh = tid & 1;
        const int no = oh ? 5 : 4;
        float po[5];
#pragma unroll
        for (int q = 0; q < 5; q++) po[q] = (q < no) ? __ldg(&bfc[oh * 4 + q]) : 0.f;
        for (int qq = 0; qq < 4; qq++) {
            __syncthreads();
#pragma unroll
            for (int q = 0; q < 8; q++) {
                const int i = tid + 128 * q;
                const int r = i >> 4, kq = (i & 15) << 2;
                float4 v = __ldcg((const float4*)&g_h7row[rg][r][qq * 64 + kq]);
                Gs[r][kq] = v.x; Gs[r][kq + 1] = v.y; Gs[r][kq + 2] = v.z; Gs[r][kq + 3] = v.w;
            }
            __syncthreads();
#pragma unroll 4
            for (int k = 0; k < 64; k++) {
                const float gv = Gs[r2][k];
#pragma unroll
                for (int q = 0; q < 5; q++)
                    if (q < no) po[q] += gv * Wfcs[(oh * 4 + q) * 256 + qq * 64 + k];
            }
        }
        __syncthreads();
#pragma unroll
        for (int q = 0; q < 5; q++)
            if (q < no) xs[r2][1 + oh * 4 + q] = po[q];
        if (bh == 0) {
#pragma unroll
            for (int q = 0; q < 5; q++)
                if (q < no)
                    out[(size_t)(row0 + r2) * (NSTEP * 9) + t * 9 + oh * 4 + q] = po[q];
        }
        __syncthreads();
    }
}

extern "C" void kernel_launch(void* const* d_in, const int* in_sizes, int n_in,
                              void* d_out, int out_size) {
    const float* states = (const float*)d_in[0];
    const float* acts   = (const float*)d_in[1];
    const float* dts    = (const float*)d_in[2];
    const float* W1     = (const float*)d_in[3];
    const float* b1     = (const float*)d_in[4];
    const float* W2     = (const float*)d_in[5];
    const float* b2     = (const float*)d_in[6];
    const float* Wih0   = (const float*)d_in[7];
    const float* Whh0   = (const float*)d_in[8];
    const float* bih0   = (const float*)d_in[9];
    const float* bhh0   = (const float*)d_in[10];
    const float* Wih    = (const float*)d_in[11];
    const float* Whh    = (const float*)d_in[12];
    const float* bih    = (const float*)d_in[13];
    const float* bhh    = (const float*)d_in[14];
    const float* Wfc    = (const float*)d_in[15];
    const float* bfc    = (const float*)d_in[16];
    float* out = (float*)d_out;

    const int sm2 = 6 * 512 * 16;            // 49152
    const int smr = (32512 + 2304) * 4;      // 139264
    cudaFuncSetAttribute(k_gemm2, cudaFuncAttributeMaxDynamicSharedMemorySize, sm2);
    cudaFuncSetAttribute(k_rollout, cudaFuncAttributeMaxDynamicSharedMemorySize, smr);

    k_prep_w<<<16384, 256>>>(Whh0, Wih, Whh);
    k_prep_w2t<<<64 * NCH2, 256>>>(W2);
    k_prep_small<<<81, 256>>>(Wih0);
    k_gemm1<<<16 * 118, 256>>>(states, acts, W1, b1);
    k_gemm2<<<512, 256, sm2>>>(b2);
    k_rollout<<<128, 128, smr>>>(states, acts, dts, bih0, bhh0,
                                 bih, bhh, Wfc, bfc, out);
}

// round 10
// speedup vs baseline: 1.2821x; 1.0223x over previous
#include <cuda_runtime.h>
#include <stdint.h>

#define B_    512
#define T_    76
#define HIST  10
#define H_    256
#define NSTEP 64
#define MLPH  15000
#define K1    130
#define NCH2  469
#define CHF   (NCH2 * 2048)

__device__ __align__(16) float g_mlpf[8][CHF];
__device__ __align__(16) float g_W2f[(size_t)64 * CHF];
__device__ __align__(16) float g_h[2][8][16][8192];   // 32-row fragment groups
__device__ __align__(16) float g_h7row[16][32][256];
__device__ __align__(16) float g_c[8][B_][H_];
__device__ __align__(16) float g_Wp[4194304];   // [l][bh16][s2][kc8][2048]
__device__ __align__(16) float g_Wih0p[16][1024];
__device__ unsigned g_prog[256];

__device__ __forceinline__ float tf32f(float x) {
    uint32_t r; asm("cvt.rna.tf32.f32 %0, %1;" : "=r"(r) : "f"(x));
    return __uint_as_float(r);
}
#define U(x) __float_as_uint(x)
__device__ __forceinline__ void mma8(float c[4], uint32_t a0, uint32_t a1, uint32_t a2, uint32_t a3,
                                     uint32_t b0, uint32_t b1) {
    asm volatile("mma.sync.aligned.m16n8k8.row.col.f32.tf32.tf32.f32 "
                 "{%0,%1,%2,%3},{%4,%5,%6,%7},{%8,%9},{%0,%1,%2,%3};\n"
                 : "+f"(c[0]), "+f"(c[1]), "+f"(c[2]), "+f"(c[3])
                 : "r"(a0), "r"(a1), "r"(a2), "r"(a3), "r"(b0), "r"(b1));
}
__device__ __forceinline__ float sigf(float x) { return __fdividef(1.f, 1.f + __expf(-x)); }
__device__ __forceinline__ float tanhf_(float x) { return 2.f * sigf(2.f * x) - 1.f; }
__device__ __forceinline__ void cpa16(void* s, const void* g) {
    uint32_t sa = (uint32_t)__cvta_generic_to_shared(s);
    asm volatile("cp.async.cg.shared.global [%0], [%1], 16;" :: "r"(sa), "l"(g));
}
#define CP_COMMIT() asm volatile("cp.async.commit_group;\n")
#define CP_WAIT(n)  asm volatile("cp.async.wait_group %0;\n" :: "n"(n))

// fragment offsets: 64-row groups (gemm2 A path) and 32-row groups (h)
__device__ __forceinline__ int hfrag(int r, int k) {
    return ((((k >> 3) * 4 + (r >> 4)) * 32 + (r & 7) * 4 + (k & 3)) << 2)
           + ((r >> 3) & 1) + (((k >> 2) & 1) << 1);
}
__device__ __forceinline__ int hfrag32(int r, int k) {
    return ((((k >> 3) * 2 + (r >> 4)) * 32 + (r & 7) * 4 + (k & 3)) << 2)
           + ((r >> 3) & 1) + (((k >> 2) & 1) << 1);
}

// gemm2 8-warp variant (unchanged)
__device__ __forceinline__ void mma_frag(const float4* Ac, const float4* Bc,
                                         float (&acc)[4][4], int wm, int wn, int lane) {
#pragma unroll
    for (int k8 = 0; k8 < 4; k8++) {
        float4 a  = Ac[(k8 * 4 + wm) * 32 + lane];
        float4 b0 = Bc[((k8 * 2 + wn) * 2 + 0) * 32 + lane];
        float4 b1 = Bc[((k8 * 2 + wn) * 2 + 1) * 32 + lane];
        mma8(acc[0], U(a.x), U(a.y), U(a.z), U(a.w), U(b0.x), U(b0.y));
        mma8(acc[1], U(a.x), U(a.y), U(a.z), U(a.w), U(b0.z), U(b0.w));
        mma8(acc[2], U(a.x), U(a.y), U(a.z), U(a.w), U(b1.x), U(b1.y));
        mma8(acc[3], U(a.x), U(a.y), U(a.z), U(a.w), U(b1.z), U(b1.w));
    }
}
// rollout 32-row variant: one 64k chunk (A 512 f4, B 1024 f4)
__device__ __forceinline__ void mma_frag32(const float4* Ac, const float4* Bc,
                                           float (&acc)[4][4], int wm, int wn, int lane) {
#pragma unroll
    for (int k8 = 0; k8 < 8; k8++) {
        float4 a = Ac[(k8 * 2 + wm) * 32 + lane];
        const float4* Bk = Bc + (k8 >> 2) * 512;
        float4 b0 = Bk[(((k8 & 3) * 2 + wn) * 2 + 0) * 32 + lane];
        float4 b1 = Bk[(((k8 & 3) * 2 + wn) * 2 + 1) * 32 + lane];
        mma8(acc[0], U(a.x), U(a.y), U(a.z), U(a.w), U(b0.x), U(b0.y));
        mma8(acc[1], U(a.x), U(a.y), U(a.z), U(a.w), U(b0.z), U(b0.w));
        mma8(acc[2], U(a.x), U(a.y), U(a.z), U(a.w), U(b1.x), U(b1.y));
        mma8(acc[3], U(a.x), U(a.y), U(a.z), U(a.w), U(b1.z), U(b1.w));
    }
}

// ---- prep: rollout weights, gate-interleaved fragments ----
__global__ void __launch_bounds__(256) k_prep_w(const float* __restrict__ Whh0,
                                                const float* __restrict__ Wih,
                                                const float* __restrict__ Whh) {
    const int idx = blockIdx.x * 256 + threadIdx.x;
    const int comp = idx & 3, c4 = (idx >> 2) & 511;
    const int lane = c4 & 31, half = (c4 >> 5) & 1, wn = (c4 >> 6) & 1, k8 = (c4 >> 7) & 3;
    const int kc = (idx >> 11) & 7, s = (idx >> 14) & 1, bh = (idx >> 15) & 15, l = (idx >> 19) & 7;
    const int gc = (wn * 4 + half * 2 + (comp >> 1)) * 8 + (lane >> 2);
    const int n = ((gc >> 3) & 3) * 256 + bh * 16 + (gc >> 5) * 8 + (gc & 7);
    const int k = kc * 32 + k8 * 8 + (comp & 1) * 4 + (lane & 3);
    float v = 0.f;
    if (l == 0) { if (s == 0) v = Whh0[n * 256 + k]; }
    else v = (s == 0) ? Whh[(size_t)(l - 1) * 262144 + n * 256 + k]
                      : Wih[(size_t)(l - 1) * 262144 + n * 256 + k];
    g_Wp[idx] = tf32f(v);
}

// ---- prep: W2 -> fragments via coalesced smem transpose ----
__global__ void __launch_bounds__(256) k_prep_w2t(const float* __restrict__ W2) {
    const int bn = blockIdx.x / NCH2, kc = blockIdx.x - bn * NCH2;
    const int tid = threadIdx.x;
    __shared__ float s[64][33];
#pragma unroll
    for (int q = 0; q < 2; q++) {
        const int f = tid + q * 256;
        const int n = f >> 3, kq = (f & 7) << 2;
        const int gk = kc * 32 + kq;
        float4 v;
        const float* p = W2 + (size_t)(bn * 64 + n) * MLPH;
        if (gk + 3 < MLPH) v = *(const float4*)(p + gk);
        else {
            v.x = (gk + 0 < MLPH) ? p[gk + 0] : 0.f;
            v.y = (gk + 1 < MLPH) ? p[gk + 1] : 0.f;
            v.z = (gk + 2 < MLPH) ? p[gk + 2] : 0.f;
            v.w = (gk + 3 < MLPH) ? p[gk + 3] : 0.f;
        }
        s[n][kq] = v.x; s[n][kq + 1] = v.y; s[n][kq + 2] = v.z; s[n][kq + 3] = v.w;
    }
    __syncthreads();
    float4* dst = ((float4*)g_W2f) + (size_t)(bn * NCH2 + kc) * 512;
#pragma unroll
    for (int q = 0; q < 2; q++) {
        const int j = tid + q * 256;
        const int lane = j & 31, half = (j >> 5) & 1, wn = (j >> 6) & 1, k8 = (j >> 7) & 3;
        float4 v; float* pv = (float*)&v;
#pragma unroll
        for (int c = 0; c < 4; c++) {
            const int gc = (wn * 4 + half * 2 + (c >> 1)) * 8 + (lane >> 2);
            const int k = k8 * 8 + (c & 1) * 4 + (lane & 3);
            pv[c] = tf32f(s[gc][k]);
        }
        dst[j] = v;
    }
}

__global__ void __launch_bounds__(256) k_prep_small(const float* __restrict__ Wih0) {
    const int i = blockIdx.x * 256 + threadIdx.x;
    if (i < 16384) {
        const int bh = i >> 10, pos = i & 1023;
        const int comp = pos & 3, c4 = pos >> 2;
        const int lane = c4 & 31, half = (c4 >> 5) & 1, wn = (c4 >> 6) & 1, k8 = (c4 >> 7) & 1;
        const int gc = (wn * 4 + half * 2 + (comp >> 1)) * 8 + (lane >> 2);
        const int n = ((gc >> 3) & 3) * 256 + bh * 16 + (gc >> 5) * 8 + (gc & 7);
        const int k = k8 * 8 + (comp & 1) * 4 + (lane & 3);
        g_Wih0p[bh][pos] = (k < 14) ? tf32f(Wih0[n * 14 + k]) : 0.f;
    } else if (i < 16384 + 4096) {
        const int j = i - 16384;
        const int rg = j >> 9, rem = j & 511;
        g_mlpf[rg][468 * 2048 + hfrag(rem >> 3, 24 + (rem & 7))] = 0.f;
    } else if (i < 16384 + 4096 + 256) {
        g_prog[i - 16384 - 4096] = 0u;
    }
}

// ---- GEMM1 ----
__global__ void __launch_bounds__(256) k_gemm1(const float* __restrict__ states,
                                               const float* __restrict__ acts,
                                               const float* __restrict__ W1,
                                               const float* __restrict__ b1) {
    const int bm = blockIdx.x & 15, bn = blockIdx.x >> 4, n0 = bn * 128;
    const int tid = threadIdx.x;
    __shared__ float enc_s[32][132];
    __shared__ float w_s[128][33];
    for (int i = tid; i < 32 * K1; i += 256) {
        const int r = i / K1, k = i % K1, b = bm * 32 + r;
        const int tt = k / 13, j = k % 13;
        enc_s[r][k] = (j < 9) ? states[(b * T_ + tt) * 12 + 3 + j]
                              : acts[(b * T_ + tt) * 4 + (j - 9)];
    }
    float acc[4][4];
#pragma unroll
    for (int a = 0; a < 4; a++)
#pragma unroll
        for (int b = 0; b < 4; b++) acc[a][b] = 0.f;
    const int tr = tid >> 5, tc = tid & 31;
    for (int k0 = 0; k0 < K1; k0 += 32) {
        const int kn = min(32, K1 - k0);
        __syncthreads();
        for (int i = tid; i < 4096; i += 256) {
            const int c = i >> 5, kk = i & 31, n = n0 + c;
            w_s[c][kk] = (kk < kn && n < MLPH) ? W1[n * K1 + k0 + kk] : 0.f;
        }
        __syncthreads();
        for (int kk = 0; kk < kn; kk++) {
            float a[4], w[4];
#pragma unroll
            for (int x = 0; x < 4; x++) a[x] = enc_s[tr + 8 * x][k0 + kk];
#pragma unroll
            for (int y = 0; y < 4; y++) w[y] = w_s[tc + 32 * y][kk];
#pragma unroll
            for (int x = 0; x < 4; x++)
#pragma unroll
                for (int y = 0; y < 4; y++) acc[x][y] += a[x] * w[y];
        }
    }
#pragma unroll
    for (int x = 0; x < 4; x++)
#pragma unroll
        for (int y = 0; y < 4; y++) {
            const int b = bm * 32 + tr + 8 * x, n = n0 + tc + 32 * y;
            if (n < MLPH)
                g_mlpf[b >> 6][(n >> 5) * 2048 + hfrag(b & 63, n & 31)] =
                    tf32f(fmaxf(acc[x][y] + b1[n], 0.f));
        }
}

// ---- GEMM2 ----
__global__ void __launch_bounds__(256, 2) k_gemm2(const float* __restrict__ b2) {
    const int bm = blockIdx.x & 7, bn = blockIdx.x >> 3;
    const int tid = threadIdx.x;
    const int warp = tid >> 5, lane = tid & 31;
    const int wm = warp >> 1, wn = warp & 1;
    const int g = lane >> 2, tq = lane & 3;
    extern __shared__ __align__(16) float4 s4[];
    float4* A4 = s4; float4* B4 = s4 + 3 * 512;
    const float4* Asrc = (const float4*)g_mlpf[bm];
    const float4* Bsrc = ((const float4*)g_W2f) + (size_t)bn * (NCH2 * 512);

    float acc[4][4];
#pragma unroll
    for (int j = 0; j < 4; j++)
#pragma unroll
        for (int d = 0; d < 4; d++) acc[j][d] = 0.f;

    auto stage = [&](int s, int c) {
        cpa16(&A4[s * 512 + tid], Asrc + (size_t)c * 512 + tid);
        cpa16(&A4[s * 512 + tid + 256], Asrc + (size_t)c * 512 + tid + 256);
        cpa16(&B4[s * 512 + tid], Bsrc + (size_t)c * 512 + tid);
        cpa16(&B4[s * 512 + tid + 256], Bsrc + (size_t)c * 512 + tid + 256);
        CP_COMMIT();
    };
    stage(0, 0); stage(1, 1);
    for (int c = 0; c < NCH2; c++) {
        if (c < NCH2 - 1) CP_WAIT(1); else CP_WAIT(0);
        __syncthreads();
        if (c + 2 < NCH2) stage((c + 2) % 3, c + 2);
        mma_frag(A4 + (c % 3) * 512, B4 + (c % 3) * 512, acc, wm, wn, lane);
    }
#pragma unroll
    for (int j = 0; j < 4; j++)
#pragma unroll
        for (int d = 0; d < 4; d++) {
            const int r = wm * 16 + g + ((d & 2) ? 8 : 0);
            const int p = (wn * 4 + j) * 8 + tq * 2 + (d & 1);
            const int n = bn * 64 + p;
            const float v = acc[j][d] + b2[n];
            const int l = n >> 9, rem = n & 511;
            if (rem < H_) g_h[1][l][bm * 2 + (r >> 5)][hfrag32(r & 31, rem)] = tf32f(v);
            else          g_c[l][bm * 64 + r][rem - H_] = v;
        }
}

// ---- rollout: 256 CTAs (16 rg x 16 bh), 2 CTA/SM, 32 rows x 64 gatecols ----
__global__ void __launch_bounds__(128, 2) k_rollout(
    const float* __restrict__ states, const float* __restrict__ acts,
    const float* __restrict__ dts,
    const float* __restrict__ bih0, const float* __restrict__ bhh0,
    const float* __restrict__ bih, const float* __restrict__ bhh,
    const float* __restrict__ Wfc, const float* __restrict__ bfc,
    float* __restrict__ out)
{
    const int rg = blockIdx.x >> 4, bh = blockIdx.x & 15;
    const int tid = threadIdx.x;
    const int warp = tid >> 5, lane = tid & 31;
    const int wm = warp >> 1, wn = warp & 1;
    const int g = lane >> 2, tq = lane & 3;
    const int row0 = rg * 32, hc0 = bh * 16;

    extern __shared__ __align__(16) float sm[];
    float4* A4 = (float4*)sm;                    // 3*512 f4
    float4* B4 = (float4*)(sm + 6144);           // 3*1024 f4
    float4* AX = (float4*)(sm + 18432);          // 128 f4
    float4* BX = (float4*)(sm + 18944);          // 256 f4
    float (*Gs)[68]   = (float(*)[68])(sm + 19968);   // 32x68
    float (*xs)[16]   = (float(*)[16])(sm + 22144);   // 32x16
    float (*bias)[64] = (float(*)[64])(sm + 22656);   // 8x64
    float* Wfcs       = sm + 23168;                    // 9*256

#pragma unroll
    for (int q = 0; q < 2; q++)
        cpa16(&BX[tid + q * 128], &((const float4*)g_Wih0p[bh])[tid + q * 128]);
    CP_COMMIT();

    for (int i = tid; i < 512; i += 128) {
        const int l = i >> 6, gc = i & 63;
        const int n = (gc >> 4) * 256 + hc0 + (gc & 15);
        bias[l][gc] = (l == 0) ? __ldg(&bih0[n]) + __ldg(&bhh0[n])
                               : __ldg(&bih[(l - 1) * 1024 + n]) + __ldg(&bhh[(l - 1) * 1024 + n]);
    }
    for (int i = tid; i < 2304; i += 128) Wfcs[i] = __ldg(&Wfc[i]);

    float c_reg[8][4];
#pragma unroll
    for (int l = 0; l < 8; l++)
#pragma unroll
        for (int d = 0; d < 4; d++) {
            const int r = wm * 16 + g + ((d & 2) ? 8 : 0);
            const int hc = wn * 8 + tq * 2 + (d & 1);
            c_reg[l][d] = __ldcg(&g_c[l][row0 + r][hc0 + hc]);
        }
    for (int i = tid; i < 288; i += 128) {
        const int r = i / 9, j = i % 9;
        xs[r][1 + j] = states[((row0 + r) * T_ + HIST) * 12 + 3 + j];
    }
    if (tid < 64) xs[tid >> 1][14 + (tid & 1)] = 0.f;
    CP_WAIT(0);
    __syncthreads();

    const float4* Wp4 = (const float4*)g_Wp;
    auto stage64 = [&](int s, const float4* Ag, const float4* Bg) {
#pragma unroll
        for (int q = 0; q < 4; q++)
            cpa16(&A4[s * 512 + tid + q * 128], Ag + tid + q * 128);
#pragma unroll
        for (int q = 0; q < 8; q++)
            cpa16(&B4[s * 1024 + tid + q * 128], Bg + tid + q * 128);
        CP_COMMIT();
    };

    for (int t = 0; t < NSTEP; t++) {
        const int cur = t & 1, old = cur ^ 1;
        if (tid < 32) xs[tid][0] = dts[(row0 + tid) * T_ + HIST + 1 + t];
        if (tid < 128) {
            const int r = tid >> 2, j = tid & 3;
            xs[r][10 + j] = acts[((row0 + r) * T_ + HIST + t) * 4 + j];
        }
        __syncthreads();

        for (int l = 0; l < 8; l++) {
            float acc[4][4];
#pragma unroll
            for (int j = 0; j < 4; j++)
#pragma unroll
                for (int d = 0; d < 4; d++) acc[j][d] = 0.f;

            const float4* Bb = Wp4 + (size_t)(l * 16 + bh) * 8192;
            const float4* Ah0 = (const float4*)&g_h[old][l][rg][0];
            const float4* Ah1 = (l > 0) ? (const float4*)&g_h[cur][l - 1][rg][0] : Ah0;
            const int nch = (l == 0) ? 4 : 8;

            stage64(0, Ah0, Bb);
            stage64(1, Ah0 + 512, Bb + 1024);

            if (l == 0) {   // x-tile (K=16)
                {
                    const int k8 = tid >> 6, mt = (tid >> 5) & 1, ln = tid & 31;
                    const int gg = ln >> 2, tt = ln & 3;
                    float4 v;
                    v.x = tf32f(xs[mt * 16 + gg][k8 * 8 + tt]);
                    v.y = tf32f(xs[mt * 16 + gg + 8][k8 * 8 + tt]);
                    v.z = tf32f(xs[mt * 16 + gg][k8 * 8 + tt + 4]);
                    v.w = tf32f(xs[mt * 16 + gg + 8][k8 * 8 + tt + 4]);
                    AX[tid] = v;
                }
                __syncthreads();
#pragma unroll
                for (int k8 = 0; k8 < 2; k8++) {
                    float4 a  = AX[(k8 * 2 + wm) * 32 + lane];
                    float4 b0 = BX[((k8 * 2 + wn) * 2 + 0) * 32 + lane];
                    float4 b1 = BX[((k8 * 2 + wn) * 2 + 1) * 32 + lane];
                    mma8(acc[0], U(a.x), U(a.y), U(a.z), U(a.w), U(b0.x), U(b0.y));
                    mma8(acc[1], U(a.x), U(a.y), U(a.z), U(a.w), U(b0.z), U(b0.w));
                    mma8(acc[2], U(a.x), U(a.y), U(a.z), U(a.w), U(b1.x), U(b1.y));
                    mma8(acc[3], U(a.x), U(a.y), U(a.z), U(a.w), U(b1.z), U(b1.w));
                }
            }

            for (int c = 0; c < nch; c++) {
                if (c < nch - 1) CP_WAIT(1); else CP_WAIT(0);
                __syncthreads();
                if (l > 0 && c == 2) {   // dependency needed before staging chunk 4
                    const unsigned tgt = (unsigned)(t * 8 + l);
                    if (tid < 16) {
                        unsigned v;
                        const unsigned* fp = &g_prog[rg * 16 + tid];
                        do {
                            asm volatile("ld.acquire.gpu.global.u32 %0, [%1];"
                                         : "=r"(v) : "l"(fp));
                            if (v >= tgt) break;
                            __nanosleep(32);
                        } while (1);
                    }
                    __syncthreads();
                }
                if (c + 2 < nch) {
                    const int c2 = c + 2;
                    const float4* Ag = (c2 < 4) ? Ah0 + c2 * 512 : Ah1 + (c2 - 4) * 512;
                    stage64(c2 % 3, Ag, Bb + c2 * 1024);
                }
                mma_frag32(A4 + (c % 3) * 512, B4 + (c % 3) * 1024, acc, wm, wn, lane);
            }

            // register LSTM epilogue
            float* hdst = &g_h[cur][l][rg][0];
#pragma unroll
            for (int d = 0; d < 4; d++) {
                const int r = wm * 16 + g + ((d & 2) ? 8 : 0);
                const int hc = wn * 8 + tq * 2 + (d & 1);
                const float iG = acc[0][d] + bias[l][hc];
                const float fG = acc[1][d] + bias[l][16 + hc];
                const float gG = acc[2][d] + bias[l][32 + hc];
                const float oG = acc[3][d] + bias[l][48 + hc];
                const float cn = sigf(fG) * c_reg[l][d] + sigf(iG) * tanhf_(gG);
                c_reg[l][d] = cn;
                const float hv = tf32f(sigf(oG) * tanhf_(cn));
                hdst[hfrag32(r, hc0 + hc)] = hv;
                if (l == 7) g_h7row[rg][r][hc0 + hc] = hv;
            }
            __syncthreads();
            if (tid == 0)
                asm volatile("st.release.gpu.global.u32 [%0], %1;"
                             :: "l"(&g_prog[rg * 16 + bh]),
                                "r"((unsigned)(t * 8 + l + 1)) : "memory");
        }

        // wait full step in this rowgroup
        if (tid < 16) {
            const unsigned tgt = (unsigned)(t * 8 + 8);
            unsigned v;
            const unsigned* fp = &g_prog[rg * 16 + tid];
            do {
                asm volatile("ld.acquire.gpu.global.u32 %0, [%1];" : "=r"(v) : "l"(fp));
                if (v >= tgt) break;
                __nanosleep(32);
            } while (1);
        }
        __syncthreads();

        // fc: 32 rows x 9 outs; r2 = tid>>2, og = tid&3 -> outs og, og+4, (og==0: 8)
        const int r2 = tid >> 2, og = tid & 3;
        float p0 = __ldg(&bfc[og]), p1 = __ldg(&bfc[og + 4]);
        float p2 = (og == 0) ? __ldg(&bfc[8]) : 0.f;
        for (int qq = 0; qq < 4; qq++) {
            __syncthreads();
#pragma unroll
            for (int q = 0; q < 4; q++) {
                const int i = tid + 128 * q;
                const int r = i >> 4, kq = (i & 15) << 2;
                float4 v = __ldcg((const float4*)&g_h7row[rg][r][qq * 64 + kq]);
                Gs[r][kq] = v.x; Gs[r][kq + 1] = v.y; Gs[r][kq + 2] = v.z; Gs[r][kq + 3] = v.w;
            }
            __syncthreads();
#pragma unroll 4
            for (int k = 0; k < 64; k++) {
                const float gv = Gs[r2][k];
                p0 += gv * Wfcs[og * 256 + qq * 64 + k];
                p1 += gv * Wfcs[(og + 4) * 256 + qq * 64 + k];
                if (og == 0) p2 += gv * Wfcs[8 * 256 + qq * 64 + k];
            }
        }
        __syncthreads();
        xs[r2][1 + og] = p0;
        xs[r2][1 + og + 4] = p1;
        if (og == 0) xs[r2][9] = p2;
        if (bh == 0) {
            out[(size_t)(row0 + r2) * (NSTEP * 9) + t * 9 + og] = p0;
            out[(size_t)(row0 + r2) * (NSTEP * 9) + t * 9 + og + 4] = p1;
            if (og == 0) out[(size_t)(row0 + r2) * (NSTEP * 9) + t * 9 + 8] = p2;
        }
        __syncthreads();
    }
}

extern "C" void kernel_launch(void* const* d_in, const int* in_sizes, int n_in,
                              void* d_out, int out_size) {
    const float* states = (const float*)d_in[0];
    const float* acts   = (const float*)d_in[1];
    const float* dts    = (const float*)d_in[2];
    const float* W1     = (const float*)d_in[3];
    const float* b1     = (const float*)d_in[4];
    const float* W2     = (const float*)d_in[5];
    const float* b2     = (const float*)d_in[6];
    const float* Wih0   = (const float*)d_in[7];
    const float* Whh0   = (const float*)d_in[8];
    const float* bih0   = (const float*)d_in[9];
    const float* bhh0   = (const float*)d_in[10];
    const float* Wih    = (const float*)d_in[11];
    const float* Whh    = (const float*)d_in[12];
    const float* bih    = (const float*)d_in[13];
    const float* bhh    = (const float*)d_in[14];
    const float* Wfc    = (const float*)d_in[15];
    const float* bfc    = (const float*)d_in[16];
    float* out = (float*)d_out;

    const int sm2 = 6 * 512 * 16;            // 49152
    const int smr = 25472 * 4;               // 101888
    cudaFuncSetAttribute(k_gemm2, cudaFuncAttributeMaxDynamicSharedMemorySize, sm2);
    cudaFuncSetAttribute(k_rollout, cudaFuncAttributeMaxDynamicSharedMemorySize, smr);

    k_prep_w<<<16384, 256>>>(Whh0, Wih, Whh);
    k_prep_w2t<<<64 * NCH2, 256>>>(W2);
    k_prep_small<<<81, 256>>>(Wih0);
    k_gemm1<<<16 * 118, 256>>>(states, acts, W1, b1);
    k_gemm2<<<512, 256, sm2>>>(b2);
    k_rollout<<<256, 128, smr>>>(states, acts, dts, bih0, bhh0,
                                 bih, bhh, Wfc, bfc, out);
}

// round 11
// speedup vs baseline: 1.5058x; 1.1745x over previous
#include <cuda_runtime.h>
#include <cuda_fp16.h>
#include <stdint.h>

#define B_    512
#define T_    76
#define HIST  10
#define H_    256
#define NSTEP 64
#define MLPH  15000
#define K1    130
#define NCH2  469
#define CHF   (NCH2 * 2048)

__device__ __align__(16) float g_mlpf[8][CHF];
__device__ __align__(16) float g_W2f[(size_t)64 * CHF];
__device__ __align__(16) __half g_hh[2][8][16][8192];   // fp16 m16n8k16 A-fragments, 32-row groups
__device__ __align__(16) float g_h7row[16][32][256];
__device__ __align__(16) float g_c[8][B_][H_];
__device__ __align__(16) __half g_Wph[4194304];          // [l][bh16][c8][4096 halfs]
__device__ __align__(16) __half g_Wih0h[16][1024];
__device__ unsigned g_prog[256];

__device__ __forceinline__ float tf32f(float x) {
    uint32_t r; asm("cvt.rna.tf32.f32 %0, %1;" : "=r"(r) : "f"(x));
    return __uint_as_float(r);
}
#define U(x) __float_as_uint(x)
__device__ __forceinline__ void mma8(float c[4], uint32_t a0, uint32_t a1, uint32_t a2, uint32_t a3,
                                     uint32_t b0, uint32_t b1) {
    asm volatile("mma.sync.aligned.m16n8k8.row.col.f32.tf32.tf32.f32 "
                 "{%0,%1,%2,%3},{%4,%5,%6,%7},{%8,%9},{%0,%1,%2,%3};\n"
                 : "+f"(c[0]), "+f"(c[1]), "+f"(c[2]), "+f"(c[3])
                 : "r"(a0), "r"(a1), "r"(a2), "r"(a3), "r"(b0), "r"(b1));
}
__device__ __forceinline__ void mma16(float c[4], uint32_t a0, uint32_t a1, uint32_t a2, uint32_t a3,
                                      uint32_t b0, uint32_t b1) {
    asm volatile("mma.sync.aligned.m16n8k16.row.col.f32.f16.f16.f32 "
                 "{%0,%1,%2,%3},{%4,%5,%6,%7},{%8,%9},{%0,%1,%2,%3};\n"
                 : "+f"(c[0]), "+f"(c[1]), "+f"(c[2]), "+f"(c[3])
                 : "r"(a0), "r"(a1), "r"(a2), "r"(a3), "r"(b0), "r"(b1));
}
__device__ __forceinline__ float sigf(float x) { return __fdividef(1.f, 1.f + __expf(-x)); }
__device__ __forceinline__ float tanhf_(float x) { return 2.f * sigf(2.f * x) - 1.f; }
__device__ __forceinline__ void cpa16(void* s, const void* g) {
    uint32_t sa = (uint32_t)__cvta_generic_to_shared(s);
    asm volatile("cp.async.cg.shared.global [%0], [%1], 16;" :: "r"(sa), "l"(g));
}
#define CP_COMMIT() asm volatile("cp.async.commit_group;\n")
#define CP_WAIT(n)  asm volatile("cp.async.wait_group %0;\n" :: "n"(n))

// tf32 64-row fragment offset (gemm1/gemm2 A path)
__device__ __forceinline__ int hfrag(int r, int k) {
    return ((((k >> 3) * 4 + (r >> 4)) * 32 + (r & 7) * 4 + (k & 3)) << 2)
           + ((r >> 3) & 1) + (((k >> 2) & 1) << 1);
}
// fp16 m16n8k16 A-fragment half-offset, 32-row group, K<=256
__device__ __forceinline__ int hfrag16(int r, int k) {
    const int f4 = ((k >> 4) * 2 + ((r >> 4) & 1)) * 32 + (r & 7) * 4 + ((k & 7) >> 1);
    const int sub = (((k >> 3) & 1) * 2 + ((r >> 3) & 1)) * 2 + (k & 1);
    return f4 * 8 + sub;
}

// gemm2 8-warp tf32 mma (unchanged)
__device__ __forceinline__ void mma_frag(const float4* Ac, const float4* Bc,
                                         float (&acc)[4][4], int wm, int wn, int lane) {
#pragma unroll
    for (int k8 = 0; k8 < 4; k8++) {
        float4 a  = Ac[(k8 * 4 + wm) * 32 + lane];
        float4 b0 = Bc[((k8 * 2 + wn) * 2 + 0) * 32 + lane];
        float4 b1 = Bc[((k8 * 2 + wn) * 2 + 1) * 32 + lane];
        mma8(acc[0], U(a.x), U(a.y), U(a.z), U(a.w), U(b0.x), U(b0.y));
        mma8(acc[1], U(a.x), U(a.y), U(a.z), U(a.w), U(b0.z), U(b0.w));
        mma8(acc[2], U(a.x), U(a.y), U(a.z), U(a.w), U(b1.x), U(b1.y));
        mma8(acc[3], U(a.x), U(a.y), U(a.z), U(a.w), U(b1.z), U(b1.w));
    }
}
// rollout fp16 chunk (K=64): A 256 uint4, B 512 uint4
__device__ __forceinline__ void mma_chunk16(const uint4* Ac, const uint4* Bc,
                                            float (&acc)[4][4], int wm, int wn, int lane) {
#pragma unroll
    for (int ks = 0; ks < 4; ks++) {
        uint4 a = Ac[(ks * 2 + wm) * 32 + lane];
        uint4 p = Bc[((ks * 2 + wn) * 2 + 0) * 32 + lane];
        uint4 q = Bc[((ks * 2 + wn) * 2 + 1) * 32 + lane];
        mma16(acc[0], a.x, a.y, a.z, a.w, p.x, p.y);
        mma16(acc[1], a.x, a.y, a.z, a.w, p.z, p.w);
        mma16(acc[2], a.x, a.y, a.z, a.w, q.x, q.y);
        mma16(acc[3], a.x, a.y, a.z, a.w, q.z, q.w);
    }
}

// ---- prep: rollout weights -> fp16 m16n8k16 B-fragments, gate-interleaved ----
__global__ void __launch_bounds__(256) k_prep_w(const float* __restrict__ Whh0,
                                                const float* __restrict__ Wih,
                                                const float* __restrict__ Whh) {
    const int idx = blockIdx.x * 256 + threadIdx.x;   // 4,194,304 halfs
    const int e = idx & 4095;
    const int c = (idx >> 12) & 7, bh = (idx >> 15) & 15, l = (idx >> 19) & 7;
    const int f4 = e >> 3, sub = e & 7;
    const int lane = f4 & 31, jp = (f4 >> 5) & 1, wn = (f4 >> 6) & 1, ks = (f4 >> 7) & 3;
    const int g = lane >> 2, tq = lane & 3;
    const int j = jp * 2 + (sub >> 2);
    const int kk = ((sub >> 1) & 1) * 8 + 2 * tq + (sub & 1);
    const int k = (c & 3) * 64 + ks * 16 + kk;
    const int s = c >> 2;                 // 0=Whh (chunks 0-3), 1=Wih (chunks 4-7)
    const int n = j * 256 + bh * 16 + wn * 8 + g;
    float v = 0.f;
    if (l == 0) { if (s == 0) v = Whh0[n * 256 + k]; }
    else v = (s == 0) ? Whh[(size_t)(l - 1) * 262144 + n * 256 + k]
                      : Wih[(size_t)(l - 1) * 262144 + n * 256 + k];
    g_Wph[idx] = __float2half_rn(v);
}

// ---- prep: W2 -> tf32 fragments via coalesced smem transpose (unchanged) ----
__global__ void __launch_bounds__(256) k_prep_w2t(const float* __restrict__ W2) {
    const int bn = blockIdx.x / NCH2, kc = blockIdx.x - bn * NCH2;
    const int tid = threadIdx.x;
    __shared__ float s[64][33];
#pragma unroll
    for (int q = 0; q < 2; q++) {
        const int f = tid + q * 256;
        const int n = f >> 3, kq = (f & 7) << 2;
        const int gk = kc * 32 + kq;
        float4 v;
        const float* p = W2 + (size_t)(bn * 64 + n) * MLPH;
        if (gk + 3 < MLPH) v = *(const float4*)(p + gk);
        else {
            v.x = (gk + 0 < MLPH) ? p[gk + 0] : 0.f;
            v.y = (gk + 1 < MLPH) ? p[gk + 1] : 0.f;
            v.z = (gk + 2 < MLPH) ? p[gk + 2] : 0.f;
            v.w = (gk + 3 < MLPH) ? p[gk + 3] : 0.f;
        }
        s[n][kq] = v.x; s[n][kq + 1] = v.y; s[n][kq + 2] = v.z; s[n][kq + 3] = v.w;
    }
    __syncthreads();
    float4* dst = ((float4*)g_W2f) + (size_t)(bn * NCH2 + kc) * 512;
#pragma unroll
    for (int q = 0; q < 2; q++) {
        const int j = tid + q * 256;
        const int lane = j & 31, half = (j >> 5) & 1, wn = (j >> 6) & 1, k8 = (j >> 7) & 3;
        float4 v; float* pv = (float*)&v;
#pragma unroll
        for (int c = 0; c < 4; c++) {
            const int gc = (wn * 4 + half * 2 + (c >> 1)) * 8 + (lane >> 2);
            const int k = k8 * 8 + (c & 1) * 4 + (lane & 3);
            pv[c] = tf32f(s[gc][k]);
        }
        dst[j] = v;
    }
}

__global__ void __launch_bounds__(256) k_prep_small(const float* __restrict__ Wih0) {
    const int i = blockIdx.x * 256 + threadIdx.x;
    if (i < 16384) {   // Wih0 -> fp16 B-fragment (single k-step, K=16 padded from 14)
        const int bh = i >> 10, e = i & 1023;
        const int f4 = e >> 3, sub = e & 7;
        const int lane = f4 & 31, jp = (f4 >> 5) & 1, wn = (f4 >> 6) & 1;
        const int g = lane >> 2, tq = lane & 3;
        const int j = jp * 2 + (sub >> 2);
        const int k = ((sub >> 1) & 1) * 8 + 2 * tq + (sub & 1);
        const int n = j * 256 + bh * 16 + wn * 8 + g;
        g_Wih0h[bh][e] = __float2half_rn((k < 14) ? Wih0[n * 14 + k] : 0.f);
    } else if (i < 16384 + 4096) {
        const int j = i - 16384;
        const int rg = j >> 9, rem = j & 511;
        g_mlpf[rg][468 * 2048 + hfrag(rem >> 3, 24 + (rem & 7))] = 0.f;
    } else if (i < 16384 + 4096 + 256) {
        g_prog[i - 16384 - 4096] = 0u;
    }
}

// ---- GEMM1 (unchanged) ----
__global__ void __launch_bounds__(256) k_gemm1(const float* __restrict__ states,
                                               const float* __restrict__ acts,
                                               const float* __restrict__ W1,
                                               const float* __restrict__ b1) {
    const int bm = blockIdx.x & 15, bn = blockIdx.x >> 4, n0 = bn * 128;
    const int tid = threadIdx.x;
    __shared__ float enc_s[32][132];
    __shared__ float w_s[128][33];
    for (int i = tid; i < 32 * K1; i += 256) {
        const int r = i / K1, k = i % K1, b = bm * 32 + r;
        const int tt = k / 13, j = k % 13;
        enc_s[r][k] = (j < 9) ? states[(b * T_ + tt) * 12 + 3 + j]
                              : acts[(b * T_ + tt) * 4 + (j - 9)];
    }
    float acc[4][4];
#pragma unroll
    for (int a = 0; a < 4; a++)
#pragma unroll
        for (int b = 0; b < 4; b++) acc[a][b] = 0.f;
    const int tr = tid >> 5, tc = tid & 31;
    for (int k0 = 0; k0 < K1; k0 += 32) {
        const int kn = min(32, K1 - k0);
        __syncthreads();
        for (int i = tid; i < 4096; i += 256) {
            const int c = i >> 5, kk = i & 31, n = n0 + c;
            w_s[c][kk] = (kk < kn && n < MLPH) ? W1[n * K1 + k0 + kk] : 0.f;
        }
        __syncthreads();
        for (int kk = 0; kk < kn; kk++) {
            float a[4], w[4];
#pragma unroll
            for (int x = 0; x < 4; x++) a[x] = enc_s[tr + 8 * x][k0 + kk];
#pragma unroll
            for (int y = 0; y < 4; y++) w[y] = w_s[tc + 32 * y][kk];
#pragma unroll
            for (int x = 0; x < 4; x++)
#pragma unroll
                for (int y = 0; y < 4; y++) acc[x][y] += a[x] * w[y];
        }
    }
#pragma unroll
    for (int x = 0; x < 4; x++)
#pragma unroll
        for (int y = 0; y < 4; y++) {
            const int b = bm * 32 + tr + 8 * x, n = n0 + tc + 32 * y;
            if (n < MLPH)
                g_mlpf[b >> 6][(n >> 5) * 2048 + hfrag(b & 63, n & 31)] =
                    tf32f(fmaxf(acc[x][y] + b1[n], 0.f));
        }
}

// ---- GEMM2 (tf32; epilogue writes h0 in fp16 fragment format) ----
__global__ void __launch_bounds__(256, 2) k_gemm2(const float* __restrict__ b2) {
    const int bm = blockIdx.x & 7, bn = blockIdx.x >> 3;
    const int tid = threadIdx.x;
    const int warp = tid >> 5, lane = tid & 31;
    const int wm = warp >> 1, wn = warp & 1;
    const int g = lane >> 2, tq = lane & 3;
    extern __shared__ __align__(16) float4 s4[];
    float4* A4 = s4; float4* B4 = s4 + 3 * 512;
    const float4* Asrc = (const float4*)g_mlpf[bm];
    const float4* Bsrc = ((const float4*)g_W2f) + (size_t)bn * (NCH2 * 512);

    float acc[4][4];
#pragma unroll
    for (int j = 0; j < 4; j++)
#pragma unroll
        for (int d = 0; d < 4; d++) acc[j][d] = 0.f;

    auto stage = [&](int s, int c) {
        cpa16(&A4[s * 512 + tid], Asrc + (size_t)c * 512 + tid);
        cpa16(&A4[s * 512 + tid + 256], Asrc + (size_t)c * 512 + tid + 256);
        cpa16(&B4[s * 512 + tid], Bsrc + (size_t)c * 512 + tid);
        cpa16(&B4[s * 512 + tid + 256], Bsrc + (size_t)c * 512 + tid + 256);
        CP_COMMIT();
    };
    stage(0, 0); stage(1, 1);
    for (int c = 0; c < NCH2; c++) {
        if (c < NCH2 - 1) CP_WAIT(1); else CP_WAIT(0);
        __syncthreads();
        if (c + 2 < NCH2) stage((c + 2) % 3, c + 2);
        mma_frag(A4 + (c % 3) * 512, B4 + (c % 3) * 512, acc, wm, wn, lane);
    }
#pragma unroll
    for (int j = 0; j < 4; j++)
#pragma unroll
        for (int d = 0; d < 4; d++) {
            const int r = wm * 16 + g + ((d & 2) ? 8 : 0);
            const int p = (wn * 4 + j) * 8 + tq * 2 + (d & 1);
            const int n = bn * 64 + p;
            const float v = acc[j][d] + b2[n];
            const int l = n >> 9, rem = n & 511;
            if (rem < H_)
                g_hh[1][l][bm * 2 + (r >> 5)][hfrag16(r & 31, rem)] = __float2half_rn(v);
            else
                g_c[l][bm * 64 + r][rem - H_] = v;
        }
}

// ---- rollout: fp16 mma, 256 CTAs (16rg x 16bh), 2 CTA/SM ----
__global__ void __launch_bounds__(128, 2) k_rollout(
    const float* __restrict__ states, const float* __restrict__ acts,
    const float* __restrict__ dts,
    const float* __restrict__ bih0, const float* __restrict__ bhh0,
    const float* __restrict__ bih, const float* __restrict__ bhh,
    const float* __restrict__ Wfc, const float* __restrict__ bfc,
    float* __restrict__ out)
{
    const int rg = blockIdx.x >> 4, bh = blockIdx.x & 15;
    const int tid = threadIdx.x;
    const int warp = tid >> 5, lane = tid & 31;
    const int wm = warp >> 1, wn = warp & 1;
    const int g = lane >> 2, tq = lane & 3;
    const int row0 = rg * 32, hc0 = bh * 16;

    extern __shared__ __align__(16) float sm[];
    uint4* A4h = (uint4*)sm;                      // 3*256 uint4 (12 KB)
    uint4* B4h = (uint4*)(sm + 3072);             // 3*512 uint4 (24 KB)
    uint4* AXh = (uint4*)(sm + 9216);             // 64 uint4
    uint4* BXh = (uint4*)(sm + 9472);             // 128 uint4
    float (*Gs)[68]   = (float(*)[68])(sm + 9984);
    float (*xs)[16]   = (float(*)[16])(sm + 12160);
    float (*bias)[64] = (float(*)[64])(sm + 12672);
    float* Wfcs       = sm + 13184;               // 2304

    cpa16(&BXh[tid], ((const uint4*)g_Wih0h[bh]) + tid);   // 128 uint4, tid<128
    CP_COMMIT();

    for (int i = tid; i < 512; i += 128) {
        const int l = i >> 6, gc = i & 63;
        const int n = (gc >> 4) * 256 + hc0 + (gc & 15);
        bias[l][gc] = (l == 0) ? __ldg(&bih0[n]) + __ldg(&bhh0[n])
                               : __ldg(&bih[(l - 1) * 1024 + n]) + __ldg(&bhh[(l - 1) * 1024 + n]);
    }
    for (int i = tid; i < 2304; i += 128) Wfcs[i] = __ldg(&Wfc[i]);

    float c_reg[8][4];
#pragma unroll
    for (int l = 0; l < 8; l++)
#pragma unroll
        for (int d = 0; d < 4; d++) {
            const int r = wm * 16 + g + ((d & 2) ? 8 : 0);
            const int hc = wn * 8 + tq * 2 + (d & 1);
            c_reg[l][d] = __ldcg(&g_c[l][row0 + r][hc0 + hc]);
        }
    for (int i = tid; i < 288; i += 128) {
        const int r = i / 9, j = i % 9;
        xs[r][1 + j] = states[((row0 + r) * T_ + HIST) * 12 + 3 + j];
    }
    if (tid < 64) xs[tid >> 1][14 + (tid & 1)] = 0.f;
    CP_WAIT(0);
    __syncthreads();

    auto stage64 = [&](int s, const uint4* Ag, const uint4* Bg) {
#pragma unroll
        for (int q = 0; q < 2; q++)
            cpa16(&A4h[s * 256 + tid + q * 128], Ag + tid + q * 128);
#pragma unroll
        for (int q = 0; q < 4; q++)
            cpa16(&B4h[s * 512 + tid + q * 128], Bg + tid + q * 128);
        CP_COMMIT();
    };

    for (int t = 0; t < NSTEP; t++) {
        const int cur = t & 1, old = cur ^ 1;
        if (tid < 32) xs[tid][0] = dts[(row0 + tid) * T_ + HIST + 1 + t];
        {
            const int r = tid >> 2, j = tid & 3;
            xs[r][10 + j] = acts[((row0 + r) * T_ + HIST + t) * 4 + j];
        }
        __syncthreads();

        for (int l = 0; l < 8; l++) {
            float acc[4][4];
#pragma unroll
            for (int j = 0; j < 4; j++)
#pragma unroll
                for (int d = 0; d < 4; d++) acc[j][d] = 0.f;

            const uint4* Bb = ((const uint4*)g_Wph) + (size_t)(l * 16 + bh) * 4096;
            const uint4* Ah0 = (const uint4*)&g_hh[old][l][rg][0];
            const uint4* Ah1 = (l > 0) ? (const uint4*)&g_hh[cur][l - 1][rg][0] : Ah0;
            const int nch = (l == 0) ? 4 : 8;

            stage64(0, Ah0, Bb);
            stage64(1, Ah0 + 256, Bb + 512);

            if (l == 0) {   // x-tile: K=16, one k-step
                if (tid < 64) {
                    const int mt = tid >> 5, ln = tid & 31;
                    const int gg = ln >> 2, tt = ln & 3;
                    uint4 v;
                    v.x = U(__uint_as_float(0)); // placeholder, set below
                    __half2 h0 = __floats2half2_rn(xs[mt * 16 + gg][2 * tt], xs[mt * 16 + gg][2 * tt + 1]);
                    __half2 h1 = __floats2half2_rn(xs[mt * 16 + gg + 8][2 * tt], xs[mt * 16 + gg + 8][2 * tt + 1]);
                    __half2 h2 = __floats2half2_rn(xs[mt * 16 + gg][8 + 2 * tt], xs[mt * 16 + gg][8 + 2 * tt + 1]);
                    __half2 h3 = __floats2half2_rn(xs[mt * 16 + gg + 8][8 + 2 * tt], xs[mt * 16 + gg + 8][8 + 2 * tt + 1]);
                    v.x = *(uint32_t*)&h0; v.y = *(uint32_t*)&h1;
                    v.z = *(uint32_t*)&h2; v.w = *(uint32_t*)&h3;
                    AXh[mt * 32 + ln] = v;
                }
                __syncthreads();
                {
                    uint4 a = AXh[wm * 32 + lane];
                    uint4 p = BXh[(wn * 2 + 0) * 32 + lane];
                    uint4 q = BXh[(wn * 2 + 1) * 32 + lane];
                    mma16(acc[0], a.x, a.y, a.z, a.w, p.x, p.y);
                    mma16(acc[1], a.x, a.y, a.z, a.w, p.z, p.w);
                    mma16(acc[2], a.x, a.y, a.z, a.w, q.x, q.y);
                    mma16(acc[3], a.x, a.y, a.z, a.w, q.z, q.w);
                }
            }

            for (int c = 0; c < nch; c++) {
                if (c < nch - 1) CP_WAIT(1); else CP_WAIT(0);
                __syncthreads();
                if (l > 0 && c == 2) {   // dependency before staging chunk 4
                    const unsigned tgt = (unsigned)(t * 8 + l);
                    if (tid < 16) {
                        unsigned v;
                        const unsigned* fp = &g_prog[rg * 16 + tid];
                        do {
                            asm volatile("ld.acquire.gpu.global.u32 %0, [%1];"
                                         : "=r"(v) : "l"(fp));
                            if (v >= tgt) break;
                            __nanosleep(32);
                        } while (1);
                    }
                    __syncthreads();
                }
                if (c + 2 < nch) {
                    const int c2 = c + 2;
                    const uint4* Ag = (c2 < 4) ? Ah0 + c2 * 256 : Ah1 + (c2 - 4) * 256;
                    stage64(c2 % 3, Ag, Bb + c2 * 512);
                }
                mma_chunk16(A4h + (c % 3) * 256, B4h + (c % 3) * 512, acc, wm, wn, lane);
            }

            // register LSTM epilogue
            __half* hdst = &g_hh[cur][l][rg][0];
#pragma unroll
            for (int d = 0; d < 4; d++) {
                const int r = wm * 16 + g + ((d & 2) ? 8 : 0);
                const int hc = wn * 8 + tq * 2 + (d & 1);
                const float iG = acc[0][d] + bias[l][hc];
                const float fG = acc[1][d] + bias[l][16 + hc];
                const float gG = acc[2][d] + bias[l][32 + hc];
                const float oG = acc[3][d] + bias[l][48 + hc];
                const float cn = sigf(fG) * c_reg[l][d] + sigf(iG) * tanhf_(gG);
                c_reg[l][d] = cn;
                const float hv = sigf(oG) * tanhf_(cn);
                hdst[hfrag16(r, hc0 + hc)] = __float2half_rn(hv);
                if (l == 7) g_h7row[rg][r][hc0 + hc] = hv;
            }
            __syncthreads();
            if (tid == 0)
                asm volatile("st.release.gpu.global.u32 [%0], %1;"
                             :: "l"(&g_prog[rg * 16 + bh]),
                                "r"((unsigned)(t * 8 + l + 1)) : "memory");
        }

        if (tid < 16) {
            const unsigned tgt = (unsigned)(t * 8 + 8);
            unsigned v;
            const unsigned* fp = &g_prog[rg * 16 + tid];
            do {
                asm volatile("ld.acquire.gpu.global.u32 %0, [%1];" : "=r"(v) : "l"(fp));
                if (v >= tgt) break;
                __nanosleep(32);
            } while (1);
        }
        __syncthreads();

        // fc: 32 rows x 9 outs
        const int r2 = tid >> 2, og = tid & 3;
        float p0 = __ldg(&bfc[og]), p1 = __ldg(&bfc[og + 4]);
        float p2 = (og == 0) ? __ldg(&bfc[8]) : 0.f;
        for (int qq = 0; qq < 4; qq++) {
            __syncthreads();
#pragma unroll
            for (int q = 0; q < 4; q++) {
                const int i = tid + 128 * q;
                const int r = i >> 4, kq = (i & 15) << 2;
                float4 v = __ldcg((const float4*)&g_h7row[rg][r][qq * 64 + kq]);
                Gs[r][kq] = v.x; Gs[r][kq + 1] = v.y; Gs[r][kq + 2] = v.z; Gs[r][kq + 3] = v.w;
            }
            __syncthreads();
#pragma unroll 4
            for (int k = 0; k < 64; k++) {
                const float gv = Gs[r2][k];
                p0 += gv * Wfcs[og * 256 + qq * 64 + k];
                p1 += gv * Wfcs[(og + 4) * 256 + qq * 64 + k];
                if (og == 0) p2 += gv * Wfcs[8 * 256 + qq * 64 + k];
            }
        }
        __syncthreads();
        xs[r2][1 + og] = p0;
        xs[r2][1 + og + 4] = p1;
        if (og == 0) xs[r2][9] = p2;
        if (bh == 0) {
            out[(size_t)(row0 + r2) * (NSTEP * 9) + t * 9 + og] = p0;
            out[(size_t)(row0 + r2) * (NSTEP * 9) + t * 9 + og + 4] = p1;
            if (og == 0) out[(size_t)(row0 + r2) * (NSTEP * 9) + t * 9 + 8] = p2;
        }
        __syncthreads();
    }
}

extern "C" void kernel_launch(void* const* d_in, const int* in_sizes, int n_in,
                              void* d_out, int out_size) {
    const float* states = (const float*)d_in[0];
    const float* acts   = (const float*)d_in[1];
    const float* dts    = (const float*)d_in[2];
    const float* W1     = (const float*)d_in[3];
    const float* b1     = (const float*)d_in[4];
    const float* W2     = (const float*)d_in[5];
    const float* b2     = (const float*)d_in[6];
    const float* Wih0   = (const float*)d_in[7];
    const float* Whh0   = (const float*)d_in[8];
    const float* bih0   = (const float*)d_in[9];
    const float* bhh0   = (const float*)d_in[10];
    const float* Wih    = (const float*)d_in[11];
    const float* Whh    = (const float*)d_in[12];
    const float* bih    = (const float*)d_in[13];
    const float* bhh    = (const float*)d_in[14];
    const float* Wfc    = (const float*)d_in[15];
    const float* bfc    = (const float*)d_in[16];
    float* out = (float*)d_out;

    const int sm2 = 6 * 512 * 16;            // 49152
    const int smr = 15488 * 4;               // 61952
    cudaFuncSetAttribute(k_gemm2, cudaFuncAttributeMaxDynamicSharedMemorySize, sm2);
    cudaFuncSetAttribute(k_rollout, cudaFuncAttributeMaxDynamicSharedMemorySize, smr);

    k_prep_w<<<16384, 256>>>(Whh0, Wih, Whh);
    k_prep_w2t<<<64 * NCH2, 256>>>(W2);
    k_prep_small<<<81, 256>>>(Wih0);
    k_gemm1<<<16 * 118, 256>>>(states, acts, W1, b1);
    k_gemm2<<<512, 256, sm2>>>(b2);
    k_rollout<<<256, 128, smr>>>(states, acts, dts, bih0, bhh0,
                                 bih, bhh, Wfc, bfc, out);
}

// round 12
// speedup vs baseline: 1.5770x; 1.0473x over previous
#include <cuda_runtime.h>
#include <cuda_fp16.h>
#include <stdint.h>

#define B_    512
#define T_    76
#define HIST  10
#define H_    256
#define NSTEP 64
#define MLPH  15000
#define K1    130
#define NC2H  235          // gemm2 64-k chunks (pad to 15040)

__device__ __align__(16) __half g_mlph[8][NC2H * 4096];          // fp16 A-fragments (64-row groups)
__device__ __align__(16) __half g_W2h[(size_t)64 * NC2H * 4096]; // fp16 B-fragments
__device__ __align__(16) __half g_hh[2][8][16][8192];            // fp16 A-fragments, 32-row groups
__device__ __align__(16) float g_h7row[16][32][256];
__device__ __align__(16) float g_c[8][B_][H_];
__device__ __align__(16) __half g_Wph[4194304];                  // [l][bh16][c8][4096]
__device__ __align__(16) __half g_Wih0h[16][1024];
__device__ unsigned g_prog[256];

#define U(x) __float_as_uint(x)
__device__ __forceinline__ void mma16(float c[4], uint32_t a0, uint32_t a1, uint32_t a2, uint32_t a3,
                                      uint32_t b0, uint32_t b1) {
    asm volatile("mma.sync.aligned.m16n8k16.row.col.f32.f16.f16.f32 "
                 "{%0,%1,%2,%3},{%4,%5,%6,%7},{%8,%9},{%0,%1,%2,%3};\n"
                 : "+f"(c[0]), "+f"(c[1]), "+f"(c[2]), "+f"(c[3])
                 : "r"(a0), "r"(a1), "r"(a2), "r"(a3), "r"(b0), "r"(b1));
}
__device__ __forceinline__ float sigf(float x) { return __fdividef(1.f, 1.f + __expf(-x)); }
__device__ __forceinline__ float tanhf_(float x) { return 2.f * sigf(2.f * x) - 1.f; }
__device__ __forceinline__ void cpa16(void* s, const void* g) {
    uint32_t sa = (uint32_t)__cvta_generic_to_shared(s);
    asm volatile("cp.async.cg.shared.global [%0], [%1], 16;" :: "r"(sa), "l"(g));
}
#define CP_COMMIT() asm volatile("cp.async.commit_group;\n")
#define CP_WAIT(n)  asm volatile("cp.async.wait_group %0;\n" :: "n"(n))
#define CP_WAIT_REM(rem) do { \
    if ((rem) >= 3) CP_WAIT(3); \
    else if ((rem) == 2) CP_WAIT(2); \
    else if ((rem) == 1) CP_WAIT(1); \
    else CP_WAIT(0); } while (0)

// fp16 m16n8k16 A-fragment half-offsets
__device__ __forceinline__ int hfrag16(int r, int k) {   // 32-row group
    const int f4 = ((k >> 4) * 2 + ((r >> 4) & 1)) * 32 + (r & 7) * 4 + ((k & 7) >> 1);
    const int sub = (((k >> 3) & 1) * 2 + ((r >> 3) & 1)) * 2 + (k & 1);
    return f4 * 8 + sub;
}
__device__ __forceinline__ int hfragA64(int r, int k) {  // 64-row group, k<64
    const int f4 = ((k >> 4) * 4 + (r >> 4)) * 32 + (r & 7) * 4 + ((k & 7) >> 1);
    const int sub = (((k >> 3) & 1) * 2 + ((r >> 3) & 1)) * 2 + (k & 1);
    return f4 * 8 + sub;
}

// rollout fp16 chunk (32 rows x 64 gc x K64): A 256 uint4, B 512 uint4; 4 warps
__device__ __forceinline__ void mma_chunk16(const uint4* Ac, const uint4* Bc,
                                            float (&acc)[4][4], int wm, int wn, int lane) {
#pragma unroll
    for (int ks = 0; ks < 4; ks++) {
        uint4 a = Ac[(ks * 2 + wm) * 32 + lane];
        uint4 p = Bc[((ks * 2 + wn) * 2 + 0) * 32 + lane];
        uint4 q = Bc[((ks * 2 + wn) * 2 + 1) * 32 + lane];
        mma16(acc[0], a.x, a.y, a.z, a.w, p.x, p.y);
        mma16(acc[1], a.x, a.y, a.z, a.w, p.z, p.w);
        mma16(acc[2], a.x, a.y, a.z, a.w, q.x, q.y);
        mma16(acc[3], a.x, a.y, a.z, a.w, q.z, q.w);
    }
}
// gemm2 fp16 chunk (64 rows x 64 cols x K64): A 512 uint4, B 512 uint4; 8 warps (4x2)
__device__ __forceinline__ void mma_chunk16g(const uint4* Ac, const uint4* Bc,
                                             float (&acc)[4][4], int wm, int wn, int lane) {
#pragma unroll
    for (int ks = 0; ks < 4; ks++) {
        uint4 a = Ac[(ks * 4 + wm) * 32 + lane];
        uint4 p = Bc[((ks * 2 + wn) * 2 + 0) * 32 + lane];
        uint4 q = Bc[((ks * 2 + wn) * 2 + 1) * 32 + lane];
        mma16(acc[0], a.x, a.y, a.z, a.w, p.x, p.y);
        mma16(acc[1], a.x, a.y, a.z, a.w, p.z, p.w);
        mma16(acc[2], a.x, a.y, a.z, a.w, q.x, q.y);
        mma16(acc[3], a.x, a.y, a.z, a.w, q.z, q.w);
    }
}

// ---- prep: rollout weights -> fp16 B-fragments, gate-interleaved ----
__global__ void __launch_bounds__(256) k_prep_w(const float* __restrict__ Whh0,
                                                const float* __restrict__ Wih,
                                                const float* __restrict__ Whh) {
    const int idx = blockIdx.x * 256 + threadIdx.x;
    const int e = idx & 4095;
    const int c = (idx >> 12) & 7, bh = (idx >> 15) & 15, l = (idx >> 19) & 7;
    const int f4 = e >> 3, sub = e & 7;
    const int lane = f4 & 31, jp = (f4 >> 5) & 1, wn = (f4 >> 6) & 1, ks = (f4 >> 7) & 3;
    const int g = lane >> 2, tq = lane & 3;
    const int j = jp * 2 + (sub >> 2);
    const int kk = ((sub >> 1) & 1) * 8 + 2 * tq + (sub & 1);
    const int k = (c & 3) * 64 + ks * 16 + kk;
    const int s = c >> 2;
    const int n = j * 256 + bh * 16 + wn * 8 + g;
    float v = 0.f;
    if (l == 0) { if (s == 0) v = Whh0[n * 256 + k]; }
    else v = (s == 0) ? Whh[(size_t)(l - 1) * 262144 + n * 256 + k]
                      : Wih[(size_t)(l - 1) * 262144 + n * 256 + k];
    g_Wph[idx] = __float2half_rn(v);
}

// ---- prep: W2 -> fp16 B-fragments via coalesced smem transpose ----
__global__ void __launch_bounds__(256) k_prep_w2t(const float* __restrict__ W2) {
    const int bn = blockIdx.x / NC2H, kc = blockIdx.x - bn * NC2H;
    const int tid = threadIdx.x;
    __shared__ float s[64][65];
#pragma unroll
    for (int q = 0; q < 4; q++) {
        const int f = tid + q * 256;
        const int n = f >> 4, kq = (f & 15) << 2;
        const int gk = kc * 64 + kq;
        float4 v;
        const float* p = W2 + (size_t)(bn * 64 + n) * MLPH;
        if (gk + 3 < MLPH) v = *(const float4*)(p + gk);
        else {
            v.x = (gk + 0 < MLPH) ? p[gk + 0] : 0.f;
            v.y = (gk + 1 < MLPH) ? p[gk + 1] : 0.f;
            v.z = (gk + 2 < MLPH) ? p[gk + 2] : 0.f;
            v.w = (gk + 3 < MLPH) ? p[gk + 3] : 0.f;
        }
        s[n][kq] = v.x; s[n][kq + 1] = v.y; s[n][kq + 2] = v.z; s[n][kq + 3] = v.w;
    }
    __syncthreads();
    uint4* dst = ((uint4*)g_W2h) + (size_t)(bn * NC2H + kc) * 512;
#pragma unroll
    for (int q = 0; q < 2; q++) {
        const int f4 = tid + q * 256;
        const int lane = f4 & 31, jp = (f4 >> 5) & 1, wn = (f4 >> 6) & 1, ks = (f4 >> 7) & 3;
        const int g = lane >> 2, tq = lane & 3;
        __half h[8];
#pragma unroll
        for (int sub = 0; sub < 8; sub++) {
            const int j = jp * 2 + (sub >> 2);
            const int kk = ((sub >> 1) & 1) * 8 + 2 * tq + (sub & 1);
            const int col = j * 16 + wn * 8 + g;
            h[sub] = __float2half_rn(s[col][ks * 16 + kk]);
        }
        dst[f4] = *(const uint4*)h;
    }
}

__global__ void __launch_bounds__(256) k_prep_small(const float* __restrict__ Wih0) {
    const int i = blockIdx.x * 256 + threadIdx.x;
    if (i < 16384) {   // Wih0 fp16 B-fragment (K=16 padded from 14)
        const int bh = i >> 10, e = i & 1023;
        const int f4 = e >> 3, sub = e & 7;
        const int lane = f4 & 31, jp = (f4 >> 5) & 1, wn = (f4 >> 6) & 1;
        const int g = lane >> 2, tq = lane & 3;
        const int j = jp * 2 + (sub >> 2);
        const int k = ((sub >> 1) & 1) * 8 + 2 * tq + (sub & 1);
        const int n = j * 256 + bh * 16 + wn * 8 + g;
        g_Wih0h[bh][e] = __float2half_rn((k < 14) ? Wih0[n * 14 + k] : 0.f);
    } else if (i < 16384 + 20480) {   // g_mlph pad k=15000..15039
        const int j = i - 16384;
        const int b = j / 40, k = MLPH + j % 40;
        g_mlph[b >> 6][(k >> 6) * 4096 + hfragA64(b & 63, k & 63)] = __float2half_rn(0.f);
    } else if (i < 16384 + 20480 + 256) {
        g_prog[i - 16384 - 20480] = 0u;
    }
}

// ---- GEMM1 (fp32 FFMA -> fp16 A-fragments) ----
__global__ void __launch_bounds__(256) k_gemm1(const float* __restrict__ states,
                                               const float* __restrict__ acts,
                                               const float* __restrict__ W1,
                                               const float* __restrict__ b1) {
    const int bm = blockIdx.x & 15, bn = blockIdx.x >> 4, n0 = bn * 128;
    const int tid = threadIdx.x;
    __shared__ float enc_s[32][132];
    __shared__ float w_s[128][33];
    for (int i = tid; i < 32 * K1; i += 256) {
        const int r = i / K1, k = i % K1, b = bm * 32 + r;
        const int tt = k / 13, j = k % 13;
        enc_s[r][k] = (j < 9) ? states[(b * T_ + tt) * 12 + 3 + j]
                              : acts[(b * T_ + tt) * 4 + (j - 9)];
    }
    float acc[4][4];
#pragma unroll
    for (int a = 0; a < 4; a++)
#pragma unroll
        for (int b = 0; b < 4; b++) acc[a][b] = 0.f;
    const int tr = tid >> 5, tc = tid & 31;
    for (int k0 = 0; k0 < K1; k0 += 32) {
        const int kn = min(32, K1 - k0);
        __syncthreads();
        for (int i = tid; i < 4096; i += 256) {
            const int c = i >> 5, kk = i & 31, n = n0 + c;
            w_s[c][kk] = (kk < kn && n < MLPH) ? W1[n * K1 + k0 + kk] : 0.f;
        }
        __syncthreads();
        for (int kk = 0; kk < kn; kk++) {
            float a[4], w[4];
#pragma unroll
            for (int x = 0; x < 4; x++) a[x] = enc_s[tr + 8 * x][k0 + kk];
#pragma unroll
            for (int y = 0; y < 4; y++) w[y] = w_s[tc + 32 * y][kk];
#pragma unroll
            for (int x = 0; x < 4; x++)
#pragma unroll
                for (int y = 0; y < 4; y++) acc[x][y] += a[x] * w[y];
        }
    }
#pragma unroll
    for (int x = 0; x < 4; x++)
#pragma unroll
        for (int y = 0; y < 4; y++) {
            const int b = bm * 32 + tr + 8 * x, n = n0 + tc + 32 * y;
            if (n < MLPH)
                g_mlph[b >> 6][(n >> 6) * 4096 + hfragA64(b & 63, n & 63)] =
                    __float2half_rn(fmaxf(acc[x][y] + b1[n], 0.f));
        }
}

// ---- GEMM2: fp16, 64-k chunks, 4-buffer pipeline, 2 CTA/SM ----
__global__ void __launch_bounds__(256, 2) k_gemm2(const float* __restrict__ b2) {
    const int bm = blockIdx.x & 7, bn = blockIdx.x >> 3;
    const int tid = threadIdx.x;
    const int warp = tid >> 5, lane = tid & 31;
    const int wm = warp >> 1, wn = warp & 1;
    const int g = lane >> 2, tq = lane & 3;
    extern __shared__ __align__(16) uint4 s4[];
    uint4* A4 = s4;               // 4*512
    uint4* B4 = s4 + 4 * 512;     // 4*512
    const uint4* Asrc = (const uint4*)g_mlph[bm];
    const uint4* Bsrc = ((const uint4*)g_W2h) + (size_t)bn * (NC2H * 512);

    float acc[4][4];
#pragma unroll
    for (int j = 0; j < 4; j++)
#pragma unroll
        for (int d = 0; d < 4; d++) acc[j][d] = 0.f;

    auto stage = [&](int s, int c) {
#pragma unroll
        for (int q = 0; q < 2; q++) {
            cpa16(&A4[s * 512 + tid + q * 256], Asrc + (size_t)c * 512 + tid + q * 256);
            cpa16(&B4[s * 512 + tid + q * 256], Bsrc + (size_t)c * 512 + tid + q * 256);
        }
        CP_COMMIT();
    };
    stage(0, 0); stage(1, 1); stage(2, 2);
    for (int c = 0; c < NC2H; c++) {
        const int rem = NC2H - 1 - c;
        if (rem >= 2) CP_WAIT(2); else if (rem == 1) CP_WAIT(1); else CP_WAIT(0);
        __syncthreads();
        if (c + 3 < NC2H) stage((c + 3) & 3, c + 3);
        mma_chunk16g(A4 + (c & 3) * 512, B4 + (c & 3) * 512, acc, wm, wn, lane);
    }
#pragma unroll
    for (int j = 0; j < 4; j++)
#pragma unroll
        for (int d = 0; d < 4; d++) {
            const int r = wm * 16 + g + ((d & 2) ? 8 : 0);
            const int col = j * 16 + wn * 8 + tq * 2 + (d & 1);
            const int n = bn * 64 + col;
            const float v = acc[j][d] + b2[n];
            const int l = n >> 9, rem2 = n & 511;
            if (rem2 < H_)
                g_hh[1][l][bm * 2 + (r >> 5)][hfrag16(r & 31, rem2)] = __float2half_rn(v);
            else
                g_c[l][bm * 64 + r][rem2 - H_] = v;
        }
}

// ---- rollout: fp16 mma, 256 CTAs, 2 CTA/SM, 5-buffer depth-4 pipeline ----
__global__ void __launch_bounds__(128, 2) k_rollout(
    const float* __restrict__ states, const float* __restrict__ acts,
    const float* __restrict__ dts,
    const float* __restrict__ bih0, const float* __restrict__ bhh0,
    const float* __restrict__ bih, const float* __restrict__ bhh,
    const float* __restrict__ Wfc, const float* __restrict__ bfc,
    float* __restrict__ out)
{
    const int rg = blockIdx.x >> 4, bh = blockIdx.x & 15;
    const int tid = threadIdx.x;
    const int warp = tid >> 5, lane = tid & 31;
    const int wm = warp >> 1, wn = warp & 1;
    const int g = lane >> 2, tq = lane & 3;
    const int row0 = rg * 32, hc0 = bh * 16;

    extern __shared__ __align__(16) float sm[];
    uint4* A4h = (uint4*)sm;                      // 5*256 uint4
    uint4* B4h = (uint4*)(sm + 5120);             // 5*512 uint4
    uint4* AXh = (uint4*)(sm + 15360);            // 64 uint4
    uint4* BXh = (uint4*)(sm + 15616);            // 128 uint4
    float (*Gs)[68]   = (float(*)[68])(sm + 16128);
    float (*xs)[16]   = (float(*)[16])(sm + 18304);
    float (*bias)[64] = (float(*)[64])(sm + 18816);
    float* Wfcs       = sm + 19328;               // 2304

    cpa16(&BXh[tid], ((const uint4*)g_Wih0h[bh]) + tid);
    CP_COMMIT();

    for (int i = tid; i < 512; i += 128) {
        const int l = i >> 6, gc = i & 63;
        const int n = (gc >> 4) * 256 + hc0 + (gc & 15);
        bias[l][gc] = (l == 0) ? __ldg(&bih0[n]) + __ldg(&bhh0[n])
                               : __ldg(&bih[(l - 1) * 1024 + n]) + __ldg(&bhh[(l - 1) * 1024 + n]);
    }
    for (int i = tid; i < 2304; i += 128) Wfcs[i] = __ldg(&Wfc[i]);

    float c_reg[8][4];
#pragma unroll
    for (int l = 0; l < 8; l++)
#pragma unroll
        for (int d = 0; d < 4; d++) {
            const int r = wm * 16 + g + ((d & 2) ? 8 : 0);
            const int hc = wn * 8 + tq * 2 + (d & 1);
            c_reg[l][d] = __ldcg(&g_c[l][row0 + r][hc0 + hc]);
        }
    for (int i = tid; i < 288; i += 128) {
        const int r = i / 9, j = i % 9;
        xs[r][1 + j] = states[((row0 + r) * T_ + HIST) * 12 + 3 + j];
    }
    if (tid < 64) xs[tid >> 1][14 + (tid & 1)] = 0.f;
    CP_WAIT(0);
    __syncthreads();

    auto stage64 = [&](int s, const uint4* Ag, const uint4* Bg) {
#pragma unroll
        for (int q = 0; q < 2; q++)
            cpa16(&A4h[s * 256 + tid + q * 128], Ag + tid + q * 128);
#pragma unroll
        for (int q = 0; q < 4; q++)
            cpa16(&B4h[s * 512 + tid + q * 128], Bg + tid + q * 128);
        CP_COMMIT();
    };

    for (int t = 0; t < NSTEP; t++) {
        const int cur = t & 1, old = cur ^ 1;
        if (tid < 32) xs[tid][0] = dts[(row0 + tid) * T_ + HIST + 1 + t];
        {
            const int r = tid >> 2, j = tid & 3;
            xs[r][10 + j] = acts[((row0 + r) * T_ + HIST + t) * 4 + j];
        }
        __syncthreads();

        for (int l = 0; l < 8; l++) {
            float acc[4][4];
#pragma unroll
            for (int j = 0; j < 4; j++)
#pragma unroll
                for (int d = 0; d < 4; d++) acc[j][d] = 0.f;

            const uint4* Bb = ((const uint4*)g_Wph) + (size_t)(l * 16 + bh) * 4096;
            const uint4* Ah0 = (const uint4*)&g_hh[old][l][rg][0];
            const uint4* Ah1 = (l > 0) ? (const uint4*)&g_hh[cur][l - 1][rg][0] : Ah0;
            const int nch = (l == 0) ? 4 : 8;

            // pre-stage all 4 dependency-free Whh chunks
            stage64(0, Ah0, Bb);
            stage64(1, Ah0 + 256, Bb + 512);
            stage64(2, Ah0 + 512, Bb + 1024);
            stage64(3, Ah0 + 768, Bb + 1536);

            if (l == 0) {   // x-tile mma
                if (tid < 64) {
                    const int mt = tid >> 5, ln = tid & 31;
                    const int gg = ln >> 2, tt = ln & 3;
                    uint4 v;
                    __half2 h0 = __floats2half2_rn(xs[mt * 16 + gg][2 * tt], xs[mt * 16 + gg][2 * tt + 1]);
                    __half2 h1 = __floats2half2_rn(xs[mt * 16 + gg + 8][2 * tt], xs[mt * 16 + gg + 8][2 * tt + 1]);
                    __half2 h2 = __floats2half2_rn(xs[mt * 16 + gg][8 + 2 * tt], xs[mt * 16 + gg][8 + 2 * tt + 1]);
                    __half2 h3 = __floats2half2_rn(xs[mt * 16 + gg + 8][8 + 2 * tt], xs[mt * 16 + gg + 8][8 + 2 * tt + 1]);
                    v.x = *(uint32_t*)&h0; v.y = *(uint32_t*)&h1;
                    v.z = *(uint32_t*)&h2; v.w = *(uint32_t*)&h3;
                    AXh[mt * 32 + ln] = v;
                }
                __syncthreads();
                {
                    uint4 a = AXh[wm * 32 + lane];
                    uint4 p = BXh[(wn * 2 + 0) * 32 + lane];
                    uint4 q = BXh[(wn * 2 + 1) * 32 + lane];
                    mma16(acc[0], a.x, a.y, a.z, a.w, p.x, p.y);
                    mma16(acc[1], a.x, a.y, a.z, a.w, p.z, p.w);
                    mma16(acc[2], a.x, a.y, a.z, a.w, q.x, q.y);
                    mma16(acc[3], a.x, a.y, a.z, a.w, q.z, q.w);
                }
            } else {
                // spin for siblings (all 4 Whh chunk loads already in flight)
                const unsigned tgt = (unsigned)(t * 8 + l);
                if (tid < 16) {
                    unsigned v;
                    const unsigned* fp = &g_prog[rg * 16 + tid];
                    do {
                        asm volatile("ld.acquire.gpu.global.u32 %0, [%1];" : "=r"(v) : "l"(fp));
                        if (v >= tgt) break;
                        __nanosleep(32);
                    } while (1);
                }
                __syncthreads();
            }

            for (int c = 0; c < nch; c++) {
                const int rem = nch - 1 - c;
                CP_WAIT_REM(rem);
                __syncthreads();
                if (c + 4 < nch) {
                    const int c2 = c + 4;
                    stage64((c2) % 5, Ah1 + (c2 - 4) * 256, Bb + c2 * 512);
                }
                mma_chunk16(A4h + (c % 5) * 256, B4h + (c % 5) * 512, acc, wm, wn, lane);
            }

            // register LSTM epilogue
            __half* hdst = &g_hh[cur][l][rg][0];
#pragma unroll
            for (int d = 0; d < 4; d++) {
                const int r = wm * 16 + g + ((d & 2) ? 8 : 0);
                const int hc = wn * 8 + tq * 2 + (d & 1);
                const float iG = acc[0][d] + bias[l][hc];
                const float fG = acc[1][d] + bias[l][16 + hc];
                const float gG = acc[2][d] + bias[l][32 + hc];
                const float oG = acc[3][d] + bias[l][48 + hc];
                const float cn = sigf(fG) * c_reg[l][d] + sigf(iG) * tanhf_(gG);
                c_reg[l][d] = cn;
                const float hv = sigf(oG) * tanhf_(cn);
                hdst[hfrag16(r, hc0 + hc)] = __float2half_rn(hv);
                if (l == 7) g_h7row[rg][r][hc0 + hc] = hv;
            }
            __syncthreads();
            if (tid == 0)
                asm volatile("st.release.gpu.global.u32 [%0], %1;"
                             :: "l"(&g_prog[rg * 16 + bh]),
                                "r"((unsigned)(t * 8 + l + 1)) : "memory");
        }

        if (tid < 16) {
            const unsigned tgt = (unsigned)(t * 8 + 8);
            unsigned v;
            const unsigned* fp = &g_prog[rg * 16 + tid];
            do {
                asm volatile("ld.acquire.gpu.global.u32 %0, [%1];" : "=r"(v) : "l"(fp));
                if (v >= tgt) break;
                __nanosleep(32);
            } while (1);
        }
        __syncthreads();

        // fc: 32 rows x 9 outs
        const int r2 = tid >> 2, og = tid & 3;
        float p0 = __ldg(&bfc[og]), p1 = __ldg(&bfc[og + 4]);
        float p2 = (og == 0) ? __ldg(&bfc[8]) : 0.f;
        for (int qq = 0; qq < 4; qq++) {
            __syncthreads();
#pragma unroll
            for (int q = 0; q < 4; q++) {
                const int i = tid + 128 * q;
                const int r = i >> 4, kq = (i & 15) << 2;
                float4 v = __ldcg((const float4*)&g_h7row[rg][r][qq * 64 + kq]);
                Gs[r][kq] = v.x; Gs[r][kq + 1] = v.y; Gs[r][kq + 2] = v.z; Gs[r][kq + 3] = v.w;
            }
            __syncthreads();
#pragma unroll 4
            for (int k = 0; k < 64; k++) {
                const float gv = Gs[r2][k];
                p0 += gv * Wfcs[og * 256 + qq * 64 + k];
                p1 += gv * Wfcs[(og + 4) * 256 + qq * 64 + k];
                if (og == 0) p2 += gv * Wfcs[8 * 256 + qq * 64 + k];
            }
        }
        __syncthreads();
        xs[r2][1 + og] = p0;
        xs[r2][1 + og + 4] = p1;
        if (og == 0) xs[r2][9] = p2;
        if (bh == 0) {
            out[(size_t)(row0 + r2) * (NSTEP * 9) + t * 9 + og] = p0;
            out[(size_t)(row0 + r2) * (NSTEP * 9) + t * 9 + og + 4] = p1;
            if (og == 0) out[(size_t)(row0 + r2) * (NSTEP * 9) + t * 9 + 8] = p2;
        }
        __syncthreads();
    }
}

extern "C" void kernel_launch(void* const* d_in, const int* in_sizes, int n_in,
                              void* d_out, int out_size) {
    const float* states = (const float*)d_in[0];
    const float* acts   = (const float*)d_in[1];
    const float* dts    = (const float*)d_in[2];
    const float* W1     = (const float*)d_in[3];
    const float* b1     = (const float*)d_in[4];
    const float* W2     = (const float*)d_in[5];
    const float* b2     = (const float*)d_in[6];
    const float* Wih0   = (const float*)d_in[7];
    const float* Whh0   = (const float*)d_in[8];
    const float* bih0   = (const float*)d_in[9];
    const float* bhh0   = (const float*)d_in[10];
    const float* Wih    = (const float*)d_in[11];
    const float* Whh    = (const float*)d_in[12];
    const float* bih    = (const float*)d_in[13];
    const float* bhh    = (const float*)d_in[14];
    const float* Wfc    = (const float*)d_in[15];
    const float* bfc    = (const float*)d_in[16];
    float* out = (float*)d_out;

    const int sm2 = 8 * 512 * 16;            // 65536
    const int smr = 21632 * 4;               // 86528
    cudaFuncSetAttribute(k_gemm2, cudaFuncAttributeMaxDynamicSharedMemorySize, sm2);
    cudaFuncSetAttribute(k_rollout, cudaFuncAttributeMaxDynamicSharedMemorySize, smr);

    k_prep_w<<<16384, 256>>>(Whh0, Wih, Whh);
    k_prep_w2t<<<64 * NC2H, 256>>>(W2);
    k_prep_small<<<146, 256>>>(Wih0);
    k_gemm1<<<16 * 118, 256>>>(states, acts, W1, b1);
    k_gemm2<<<512, 256, sm2>>>(b2);
    k_rollout<<<256, 128, smr>>>(states, acts, dts, bih0, bhh0,
                                 bih, bhh, Wfc, bfc, out);
}